// round 15
// baseline (speedup 1.0000x reference)
#include <cuda_runtime.h>
#include <cuda_bf16.h>
#include <cuda_fp16.h>
#include <cstdint>
#include <cstddef>

#define BATCH 64
#define TDEC  256
#define TENC  1152
#define MELD  80
#define ATTD  128
#define RNND  1024
#define GATE4 4096
#define KX    1280
#define ROWS  16384

#define MELS_CNT   (BATCH*TDEC*MELD)
#define GATES_OFF  MELS_CNT
#define ALIGNS_OFF (MELS_CNT + BATCH*TDEC)

#define NBLK 128

// fp32 scratch
__device__ float g_P1 [ROWS * 256];
__device__ float g_P2 [ROWS * 256];
__device__ float g_Q  [ROWS * ATTD];
__device__ float g_PM [BATCH * TENC * ATTD];
__device__ float g_E  [(size_t)ROWS * TENC];
__device__ float g_X  [(size_t)ROWS * KX];
__device__ float g_G1 [(size_t)ROWS * GATE4];   // transposed: [t][4096][64]
__device__ float g_H  [(size_t)ROWS * RNND];
// fragment scratch (bf16 hi/lo)
__device__ uint4 g_AfHi[80 * 1024 * 32];
__device__ uint4 g_AfLo[80 * 1024 * 32];
__device__ uint4 g_BfIh[80 * 512 * 32];
__device__ uint4 g_WfHh[64 * 512 * 32];
__device__ uint4 g_BfSm[16 * 32 * 32];
__device__ uint4 g_WaHi[64 * 72 * 16 * 32];
__device__ uint4 g_WaLo[64 * 72 * 16 * 32];
__device__ uint4 g_BfPM[64 * 72 * 16 * 32];
__device__ uint4 g_HfHi[2 * 64 * 4 * 32];
__device__ uint4 g_HfLo[2 * 64 * 4 * 32];
__device__ unsigned int g_bar;

// ---------- helpers ----------
__device__ __forceinline__ void mma16(float* c, uint32_t a0, uint32_t a1, uint32_t a2,
                                      uint32_t a3, uint32_t b0, uint32_t b1) {
    asm volatile(
        "mma.sync.aligned.m16n8k16.row.col.f32.bf16.bf16.f32 "
        "{%0,%1,%2,%3}, {%4,%5,%6,%7}, {%8,%9}, {%0,%1,%2,%3};\n"
        : "+f"(c[0]), "+f"(c[1]), "+f"(c[2]), "+f"(c[3])
        : "r"(a0), "r"(a1), "r"(a2), "r"(a3), "r"(b0), "r"(b1));
}

__device__ __forceinline__ void pack2(float e, float o, uint32_t& hi, uint32_t& lo) {
    __nv_bfloat16 eh = __float2bfloat16_rn(e);
    __nv_bfloat16 oh = __float2bfloat16_rn(o);
    __nv_bfloat16 el = __float2bfloat16_rn(e - __bfloat162float(eh));
    __nv_bfloat16 ol = __float2bfloat16_rn(o - __bfloat162float(oh));
    __nv_bfloat162 hv; hv.x = eh; hv.y = oh;
    __nv_bfloat162 lv; lv.x = el; lv.y = ol;
    hi = *reinterpret_cast<uint32_t*>(&hv);
    lo = *reinterpret_cast<uint32_t*>(&lv);
}

__device__ __forceinline__ float fast_tanh(float x) {
    return 1.f - __fdividef(2.f, __expf(2.f * x) + 1.f);
}

#define CP_ASYNC16(saddr, gptr) \
    asm volatile("cp.async.cg.shared.global [%0], [%1], 16;" \
                 :: "r"(saddr), "l"(gptr) : "memory")
#define CP_COMMIT() asm volatile("cp.async.commit_group;" ::: "memory")
#define CP_WAIT1()  asm volatile("cp.async.wait_group 1;" ::: "memory")
#define CP_WAIT0()  asm volatile("cp.async.wait_group 0;" ::: "memory")

// ---------- prep/pack ----------
__global__ void zero_bar_kernel() { if (threadIdx.x == 0) g_bar = 0u; }

__global__ void pack_bfrag_kernel(const float* __restrict__ W, uint4* __restrict__ out,
                                  int kbcnt, int nbcnt, int ldw) {
    int i = blockIdx.x * blockDim.x + threadIdx.x;
    if (i < kbcnt * nbcnt * 32) {
        int lane = i & 31;
        int t32 = i >> 5;
        int nb = t32 % nbcnt;
        int kb = t32 / nbcnt;
        int q = lane & 3, gr = lane >> 2;
        int col = nb * 8 + gr;
        int k2a = kb * 8 + q, k2b = k2a + 4;
        float wa0 = W[(size_t)(2 * k2a) * ldw + col];
        float wa1 = W[(size_t)(2 * k2a + 1) * ldw + col];
        float wb0 = W[(size_t)(2 * k2b) * ldw + col];
        float wb1 = W[(size_t)(2 * k2b + 1) * ldw + col];
        uint32_t h0, l0, h1, l1;
        pack2(wa0, wa1, h0, l0);
        pack2(wb0, wb1, h1, l1);
        out[i] = make_uint4(h0, h1, l0, l1);
    }
}

__global__ void pack_afrag_kernel(const float* __restrict__ A, int lda,
                                  int kbcnt, int mtcnt,
                                  uint4* __restrict__ outHi, uint4* __restrict__ outLo) {
    int i = blockIdx.x * blockDim.x + threadIdx.x;
    if (i < kbcnt * mtcnt * 32) {
        int lane = i & 31;
        int t32 = i >> 5;
        int mt = t32 % mtcnt;
        int kb = t32 / mtcnt;
        int q = lane & 3, gr = lane >> 2;
        int m0 = mt * 16 + gr, m1 = m0 + 8;
        int k2a = kb * 8 + q, k2b = k2a + 4;
        uint32_t h[4], l[4];
        pack2(A[(size_t)m0 * lda + 2 * k2a], A[(size_t)m0 * lda + 2 * k2a + 1], h[0], l[0]);
        pack2(A[(size_t)m1 * lda + 2 * k2a], A[(size_t)m1 * lda + 2 * k2a + 1], h[1], l[1]);
        pack2(A[(size_t)m0 * lda + 2 * k2b], A[(size_t)m0 * lda + 2 * k2b + 1], h[2], l[2]);
        pack2(A[(size_t)m1 * lda + 2 * k2b], A[(size_t)m1 * lda + 2 * k2b + 1], h[3], l[3]);
        outHi[i] = make_uint4(h[0], h[1], h[2], h[3]);
        outLo[i] = make_uint4(l[0], l[1], l[2], l[3]);
    }
}

__global__ void prep_pin_frag_kernel(const float* __restrict__ mel) {
    int i = blockIdx.x * blockDim.x + threadIdx.x;
    if (i < 5 * 1024 * 32) {
        int lane = i & 31;
        int t32 = i >> 5;
        int mt = t32 & 1023;
        int kb = t32 >> 10;
        int q = lane & 3, gr = lane >> 2;
        int k2a = kb * 8 + q, k2b = k2a + 4;
        uint32_t h[4], l[4];
#pragma unroll
        for (int half = 0; half < 2; half++) {
            int m = mt * 16 + gr + half * 8;
            int t = m >> 6, b = m & 63;
            const float* src = mel + ((size_t)b * TDEC + t) * MELD;
            float v0a = (t == 0) ? 0.f : src[2 * k2a];
            float v1a = (t == 0) ? 0.f : src[2 * k2a + 1];
            float v0b = (t == 0) ? 0.f : src[2 * k2b];
            float v1b = (t == 0) ? 0.f : src[2 * k2b + 1];
            pack2(v0a, v1a, h[half], l[half]);
            pack2(v0b, v1b, h[2 + half], l[2 + half]);
        }
        g_AfHi[i] = make_uint4(h[0], h[1], h[2], h[3]);
        g_AfLo[i] = make_uint4(l[0], l[1], l[2], l[3]);
    }
}

__global__ void pack_w_kernel(const float* __restrict__ aligns) {
    int z = blockIdx.y;
    int i = blockIdx.x * blockDim.x + threadIdx.x;   // < 72*16*32
    int lane = i & 31;
    int t32 = i >> 5;
    int mt = t32 & 15;
    int kb = t32 >> 4;
    int q = lane & 3, gr = lane >> 2;
    int m0 = mt * 16 + gr, m1 = m0 + 8;
    int k2a = kb * 8 + q, k2b = k2a + 4;
    const float* A = aligns + (size_t)z * 256 * TENC;
    uint32_t h[4], l[4];
    pack2(A[(size_t)m0 * TENC + 2 * k2a], A[(size_t)m0 * TENC + 2 * k2a + 1], h[0], l[0]);
    pack2(A[(size_t)m1 * TENC + 2 * k2a], A[(size_t)m1 * TENC + 2 * k2a + 1], h[1], l[1]);
    pack2(A[(size_t)m0 * TENC + 2 * k2b], A[(size_t)m0 * TENC + 2 * k2b + 1], h[2], l[2]);
    pack2(A[(size_t)m1 * TENC + 2 * k2b], A[(size_t)m1 * TENC + 2 * k2b + 1], h[3], l[3]);
    size_t o = (size_t)z * 36864 + i;
    g_WaHi[o] = make_uint4(h[0], h[1], h[2], h[3]);
    g_WaLo[o] = make_uint4(l[0], l[1], l[2], l[3]);
}

__global__ void pack_pm_kernel(const float* __restrict__ PM) {
    int z = blockIdx.y;
    int i = blockIdx.x * blockDim.x + threadIdx.x;
    int lane = i & 31;
    int t32 = i >> 5;
    int nb = t32 & 15;
    int kb = t32 >> 4;
    int q = lane & 3, gr = lane >> 2;
    int col = nb * 8 + gr;
    int k2a = kb * 8 + q, k2b = k2a + 4;
    const float* W = PM + (size_t)z * TENC * ATTD;
    float wa0 = W[(size_t)(2 * k2a) * ATTD + col];
    float wa1 = W[(size_t)(2 * k2a + 1) * ATTD + col];
    float wb0 = W[(size_t)(2 * k2b) * ATTD + col];
    float wb1 = W[(size_t)(2 * k2b + 1) * ATTD + col];
    uint32_t h0, l0, h1, l1;
    pack2(wa0, wa1, h0, l0);
    pack2(wb0, wb1, h1, l1);
    g_BfPM[(size_t)z * 36864 + i] = make_uint4(h0, h1, l0, l1);
}

// ---------- bf16 hi/lo 3-term GEMM, cp.async 2-stage pipeline ----------
// Block = 256 rows x 128 cols. grid (ncols/128, M/256, nbatch).
// smem/stage: AHi[16mt][32] | ALo[16mt][32] | B[16nb][32] = 1536 uint4 = 24KB; 2 stages.
__global__ __launch_bounds__(256, 1) void gemm_bf3_kernel(
    const uint4* __restrict__ AfHi, const uint4* __restrict__ AfLo,
    const uint4* __restrict__ Bf, float* __restrict__ C, long ldc,
    int kbcnt, int nbcnt, int mtcnt,
    const float* __restrict__ bias1, const float* __restrict__ bias2,
    int relu, int omode, long aZoff, long bZoff, long cZoff)
{
    extern __shared__ uint4 smem[];   // 2 * 1536 uint4
    AfHi += (size_t)blockIdx.z * aZoff;
    AfLo += (size_t)blockIdx.z * aZoff;
    Bf   += (size_t)blockIdx.z * bZoff;
    C    += (size_t)blockIdx.z * cZoff;

    int tid = threadIdx.x;
    int warp = tid >> 5, lane = tid & 31;
    int wm = warp & 3, wn = warp >> 2;
    int gr = lane >> 2, q = lane & 3;
    int bm = blockIdx.y * 256, bn = blockIdx.x * 128;
    int mtBase0 = bm >> 4;
    int nbBase0 = bn >> 3;

    uint32_t smem_u32;
    {
        uint64_t tmp = __cvta_generic_to_shared(smem);
        smem_u32 = (uint32_t)tmp;
    }

    float acc[4][8][4];
#pragma unroll
    for (int i = 0; i < 4; i++)
#pragma unroll
        for (int j = 0; j < 8; j++)
#pragma unroll
            for (int r = 0; r < 4; r++) acc[i][j][r] = 0.f;

    // per-thread load slots: e = tid, tid+256, ..., tid+1280
    auto issue_stage = [&](int kb, int s) {
        uint32_t sb = smem_u32 + (uint32_t)s * 1536u * 16u;
#pragma unroll
        for (int p = 0; p < 6; p++) {
            int e = tid + p * 256;
            const uint4* src;
            if (e < 512)
                src = &AfHi[((size_t)kb * mtcnt + mtBase0 + (e >> 5)) * 32 + (e & 31)];
            else if (e < 1024)
                src = &AfLo[((size_t)kb * mtcnt + mtBase0 + ((e - 512) >> 5)) * 32 + (e & 31)];
            else
                src = &Bf[((size_t)kb * nbcnt + nbBase0 + ((e - 1024) >> 5)) * 32 + (e & 31)];
            CP_ASYNC16(sb + (uint32_t)e * 16u, src);
        }
    };

    issue_stage(0, 0);
    CP_COMMIT();

    for (int kb = 0; kb < kbcnt; kb++) {
        int cur = kb & 1;
        if (kb + 1 < kbcnt) {
            issue_stage(kb + 1, cur ^ 1);
            CP_COMMIT();
            CP_WAIT1();
        } else {
            CP_WAIT0();
        }
        __syncthreads();

        const uint4* sBase = smem + (size_t)cur * 1536;
        uint4 ah[4], al[4];
#pragma unroll
        for (int i = 0; i < 4; i++) {
            ah[i] = sBase[(wm * 4 + i) * 32 + lane];
            al[i] = sBase[512 + (wm * 4 + i) * 32 + lane];
        }
#pragma unroll
        for (int j = 0; j < 8; j++) {
            uint4 bv = sBase[1024 + (wn * 8 + j) * 32 + lane];
#pragma unroll
            for (int i = 0; i < 4; i++) {
                mma16(acc[i][j], ah[i].x, ah[i].y, ah[i].z, ah[i].w, bv.x, bv.y);
                mma16(acc[i][j], ah[i].x, ah[i].y, ah[i].z, ah[i].w, bv.z, bv.w);
                mma16(acc[i][j], al[i].x, al[i].y, al[i].z, al[i].w, bv.x, bv.y);
            }
        }
        __syncthreads();
    }

#pragma unroll
    for (int i = 0; i < 4; i++) {
        int r0 = bm + (wm * 4 + i) * 16 + gr;
#pragma unroll
        for (int j = 0; j < 8; j++) {
            int c = bn + wn * 64 + j * 8 + 2 * q;
            float bb0 = 0.f, bb1 = 0.f;
            if (bias1) { bb0 += bias1[c]; bb1 += bias1[c + 1]; }
            if (bias2) { bb0 += bias2[c]; bb1 += bias2[c + 1]; }
            float v00 = acc[i][j][0] + bb0, v01 = acc[i][j][1] + bb1;
            float v10 = acc[i][j][2] + bb0, v11 = acc[i][j][3] + bb1;
            if (relu) {
                v00 = fmaxf(v00, 0.f); v01 = fmaxf(v01, 0.f);
                v10 = fmaxf(v10, 0.f); v11 = fmaxf(v11, 0.f);
            }
            if (omode == 2) {
                int r1 = r0 + 8;
                size_t o00 = ((size_t)(r0 >> 6) * GATE4 + c) * 64 + (r0 & 63);
                size_t o10 = ((size_t)(r1 >> 6) * GATE4 + c) * 64 + (r1 & 63);
                C[o00]      = v00;
                C[o00 + 64] = v01;
                C[o10]      = v10;
                C[o10 + 64] = v11;
            } else {
                C[(size_t)r0 * ldc + c]           = v00;
                C[(size_t)r0 * ldc + c + 1]       = v01;
                C[(size_t)(r0 + 8) * ldc + c]     = v10;
                C[(size_t)(r0 + 8) * ldc + c + 1] = v11;
            }
        }
    }
}

// ---------- fp32 sgemm (mel projection only) ----------
__global__ __launch_bounds__(256, 2) void sgemm_kernel(
    const float* __restrict__ A, int lda,
    const float* __restrict__ B, int ldb,
    float* __restrict__ C, int ldc,
    int M, int N, int K,
    const float* __restrict__ bias1, int rowperm)
{
    __shared__ float As[8][128];
    __shared__ float Bs[8][128];
    int bm = blockIdx.y * 128, bn = blockIdx.x * 128;
    int tid = threadIdx.x;
    int tx = tid & 15, ty = tid >> 4;
    float acc[8][8];
#pragma unroll
    for (int i = 0; i < 8; i++)
#pragma unroll
        for (int j = 0; j < 8; j++) acc[i][j] = 0.f;

    int a_row = tid >> 1, a_k4 = (tid & 1) * 4;
    int b_kk = tid >> 5, b_c4 = (tid & 31) * 4;

    for (int k0 = 0; k0 < K; k0 += 8) {
        float4 av = *reinterpret_cast<const float4*>(A + (size_t)(bm + a_row) * lda + k0 + a_k4);
        float4 bv = make_float4(0.f, 0.f, 0.f, 0.f);
        if (bn + b_c4 < N)
            bv = *reinterpret_cast<const float4*>(B + (size_t)(k0 + b_kk) * ldb + bn + b_c4);
        __syncthreads();
        As[a_k4 + 0][a_row] = av.x; As[a_k4 + 1][a_row] = av.y;
        As[a_k4 + 2][a_row] = av.z; As[a_k4 + 3][a_row] = av.w;
        *reinterpret_cast<float4*>(&Bs[b_kk][b_c4]) = bv;
        __syncthreads();
#pragma unroll
        for (int kk = 0; kk < 8; kk++) {
            float ar[8], br[8];
            float4 a0 = *reinterpret_cast<const float4*>(&As[kk][ty * 8]);
            float4 a1 = *reinterpret_cast<const float4*>(&As[kk][ty * 8 + 4]);
            float4 b0 = *reinterpret_cast<const float4*>(&Bs[kk][tx * 8]);
            float4 b1 = *reinterpret_cast<const float4*>(&Bs[kk][tx * 8 + 4]);
            ar[0]=a0.x;ar[1]=a0.y;ar[2]=a0.z;ar[3]=a0.w;ar[4]=a1.x;ar[5]=a1.y;ar[6]=a1.z;ar[7]=a1.w;
            br[0]=b0.x;br[1]=b0.y;br[2]=b0.z;br[3]=b0.w;br[4]=b1.x;br[5]=b1.y;br[6]=b1.z;br[7]=b1.w;
#pragma unroll
            for (int i = 0; i < 8; i++)
#pragma unroll
                for (int j = 0; j < 8; j++)
                    acc[i][j] = fmaf(ar[i], br[j], acc[i][j]);
        }
    }
#pragma unroll
    for (int i = 0; i < 8; i++) {
        int row = bm + ty * 8 + i;
        int orow = rowperm ? ((row & 63) * TDEC + (row >> 6)) : row;
#pragma unroll
        for (int j = 0; j < 8; j++) {
            int col = bn + tx * 8 + j;
            if (col < N) {
                float v = acc[i][j];
                if (bias1) v += bias1[col];
                C[(size_t)orow * ldc + col] = v;
            }
        }
    }
}

// ---------- attention: logits via f16x2 tanh ----------
__global__ __launch_bounds__(256) void att_e_kernel(
    const float* __restrict__ Q, const float* __restrict__ PM,
    const float* __restrict__ v, float* __restrict__ E)
{
    __shared__ __half2 pm_s[64][65];
    __shared__ __half2 qs[4][64];
    __shared__ float v_s[128];
    int b = blockIdx.y, te0 = blockIdx.x * 64, tid = threadIdx.x;
    if (tid < 128) v_s[tid] = v[tid];
    for (int i = tid; i < 64 * 64; i += 256) {
        int r = i >> 6, c2 = i & 63;
        float2 f = *reinterpret_cast<const float2*>(
            PM + ((size_t)b * TENC + te0 + r) * ATTD + 2 * c2);
        pm_s[r][c2] = __floats2half2_rn(f.x, f.y);
    }
    int te = tid & 63, qq = tid >> 6;
    __syncthreads();
    for (int t0 = 0; t0 < TDEC; t0 += 4) {
        {
            int q = tid >> 6, c2 = tid & 63;
            float2 f = *reinterpret_cast<const float2*>(
                Q + ((size_t)(t0 + q) * 64 + b) * ATTD + 2 * c2);
            qs[q][c2] = __floats2half2_rn(f.x, f.y);
        }
        __syncthreads();
        float e = 0.f;
#pragma unroll 4
        for (int d2 = 0; d2 < 64; d2++) {
            __half2 x2 = __hadd2(qs[qq][d2], pm_s[te][d2]);
            uint32_t xi = *reinterpret_cast<uint32_t*>(&x2);
            uint32_t ti;
            asm("tanh.approx.f16x2 %0, %1;" : "=r"(ti) : "r"(xi));
            __half2 t2 = *reinterpret_cast<__half2*>(&ti);
            float2 tf = __half22float2(t2);
            e = fmaf(v_s[2 * d2], tf.x, e);
            e = fmaf(v_s[2 * d2 + 1], tf.y, e);
        }
        E[((size_t)(t0 + qq) * 64 + b) * TENC + te0 + te] = e;
        __syncthreads();
    }
}

__global__ __launch_bounds__(256) void att_softmax_kernel(
    const float* __restrict__ E, float* __restrict__ X, float* __restrict__ aligns)
{
    __shared__ float w_s[8][TENC];
    __shared__ float inv_s[8];
    int b = blockIdx.y, t0 = blockIdx.x * 8, tid = threadIdx.x;
    int warp = tid >> 5, lane = tid & 31;
    {
        int t = t0 + warp;
        size_t eb = ((size_t)t * 64 + b) * TENC;
        float m = -1e30f;
        for (int te = lane; te < TENC; te += 32) m = fmaxf(m, E[eb + te]);
#pragma unroll
        for (int o = 16; o; o >>= 1) m = fmaxf(m, __shfl_xor_sync(0xffffffffu, m, o));
        float s = 0.f;
        for (int te = lane; te < TENC; te += 32) {
            float w = __expf(E[eb + te] - m);
            w_s[warp][te] = w; s += w;
        }
#pragma unroll
        for (int o = 16; o; o >>= 1) s += __shfl_xor_sync(0xffffffffu, s, o);
        if (lane == 0) inv_s[warp] = 1.f / s;
    }
    __syncthreads();
    for (int i = tid; i < 8 * TENC; i += 256) {
        int q = i / TENC, te = i - q * TENC;
        float wv = w_s[q][te] * inv_s[q];
        int t = t0 + q;
        aligns[((size_t)b * TDEC + t) * TENC + te] = wv;
        X[((size_t)t * 64 + b) * KX + ATTD + te] = wv;
    }
}

// ---------- persistent LSTM: kb-split warps (R12 structure) ----------
__global__ __launch_bounds__(256, 1) void lstm_persistent_kernel(
    const float* __restrict__ G1, float* __restrict__ H)
{
    extern __shared__ uint4 smW[];           // [64 kb][4 gate][32 lane] = 128 KB
    __shared__ float st2[2][64][36];

    int tid = threadIdx.x;
    int warp = tid >> 5, lane = tid & 31;
    int gr = lane >> 2, q = lane & 3;
    int rt = warp & 3, kh = warp >> 2;
    int u0 = blockIdx.x * 8;
    int base = u0 >> 3;

    for (int i = tid; i < 64 * 4 * 32; i += 256) {
        int lane2 = i & 31, gate = (i >> 5) & 3, kb = i >> 7;
        smW[i] = __ldg(&g_WfHh[((size_t)kb * 512 + gate * 128 + base) * 32 + lane2]);
    }
    __syncthreads();

    int pb = tid & 63, pq = tid >> 6;
    float creg[2] = {0.f, 0.f};

    int p = (u0 >> 1) + pq;
    int kbW = p >> 3, qq = p & 7;
    int rtW = pb >> 4, rin = pb & 15;
    int comp = (qq < 4) ? ((rin < 8) ? 0 : 1) : ((rin < 8) ? 2 : 3);
    int laneW = (rin & 7) * 4 + (qq & 3);
    int fragIdx = ((kbW * 4 + rtW) * 32 + laneW) * 4 + comp;

    int kbeg = kh * 32;

    for (int t = 0; t < TDEC; t++) {
        float g1p[2][4];
        {
            size_t gb = (size_t)t * GATE4 * 64;
#pragma unroll
            for (int s = 0; s < 2; s++) {
                int u = u0 + 2 * pq + s;
                g1p[s][0] = __ldg(G1 + gb + (size_t)(0 * RNND + u) * 64 + pb);
                g1p[s][1] = __ldg(G1 + gb + (size_t)(1 * RNND + u) * 64 + pb);
                g1p[s][2] = __ldg(G1 + gb + (size_t)(2 * RNND + u) * 64 + pb);
                g1p[s][3] = __ldg(G1 + gb + (size_t)(3 * RNND + u) * 64 + pb);
            }
        }

        float acc[4][4];
#pragma unroll
        for (int g = 0; g < 4; g++)
#pragma unroll
            for (int r = 0; r < 4; r++) acc[g][r] = 0.f;

        if (t > 0) {
            int bufR = (t - 1) & 1;
            const uint4* AH = g_HfHi + (size_t)bufR * 64 * 4 * 32;
            const uint4* AL = g_HfLo + (size_t)bufR * 64 * 4 * 32;
#pragma unroll 8
            for (int kk = 0; kk < 32; kk++) {
                int kb = kbeg + kk;
                uint4 ah = __ldcg(AH + (kb * 4 + rt) * 32 + lane);
                uint4 al = __ldcg(AL + (kb * 4 + rt) * 32 + lane);
#pragma unroll
                for (int g = 0; g < 4; g++) {
                    uint4 b = smW[kb * 128 + g * 32 + lane];
                    mma16(acc[g], ah.x, ah.y, ah.z, ah.w, b.x, b.y);
                    mma16(acc[g], ah.x, ah.y, ah.z, ah.w, b.z, b.w);
                    mma16(acc[g], al.x, al.y, al.z, al.w, b.x, b.y);
                }
            }
        }

#pragma unroll
        for (int g = 0; g < 4; g++) {
            int c = g * 8 + 2 * q;
            int r0 = rt * 16 + gr;
            st2[kh][r0][c]         = acc[g][0];
            st2[kh][r0][c + 1]     = acc[g][1];
            st2[kh][r0 + 8][c]     = acc[g][2];
            st2[kh][r0 + 8][c + 1] = acc[g][3];
        }
        __syncthreads();

        float hpair[2];
#pragma unroll
        for (int s = 0; s < 2; s++) {
            int ul = 2 * pq + s;
            int u = u0 + ul;
            float gi = st2[0][pb][ul]      + st2[1][pb][ul]      + g1p[s][0];
            float gf = st2[0][pb][8 + ul]  + st2[1][pb][8 + ul]  + g1p[s][1];
            float gg = st2[0][pb][16 + ul] + st2[1][pb][16 + ul] + g1p[s][2];
            float go = st2[0][pb][24 + ul] + st2[1][pb][24 + ul] + g1p[s][3];
            float i_ = 1.f / (1.f + __expf(-gi));
            float f_ = 1.f / (1.f + __expf(-gf));
            float g_ = fast_tanh(gg);
            float o_ = 1.f / (1.f + __expf(-go));
            float cn = f_ * creg[s] + i_ * g_;
            creg[s] = cn;
            float hn = o_ * fast_tanh(cn);
            hpair[s] = hn;
            H[((size_t)t * 64 + pb) * RNND + u] = hn;
        }
        {
            int bufW = t & 1;
            uint32_t hi, lo;
            pack2(hpair[0], hpair[1], hi, lo);
            size_t off = (size_t)bufW * 64 * 4 * 32 * 4 + fragIdx;
            reinterpret_cast<uint32_t*>(g_HfHi)[off] = hi;
            reinterpret_cast<uint32_t*>(g_HfLo)[off] = lo;
        }
        __syncthreads();
        if (tid == 0) {
            asm volatile("red.release.gpu.global.add.u32 [%0], %1;"
                         :: "l"(&g_bar), "r"(1u) : "memory");
            unsigned tgt = (unsigned)NBLK * (unsigned)(t + 1);
            unsigned v;
            do {
                asm volatile("ld.global.acquire.gpu.u32 %0, [%1];" : "=r"(v) : "l"(&g_bar));
            } while (v < tgt);
        }
        __syncthreads();
    }
}

__global__ __launch_bounds__(256) void stop_kernel(
    const float* __restrict__ H, const float* __restrict__ sw,
    const float* __restrict__ sb, float* __restrict__ gout)
{
    int row = blockIdx.x * 8 + (threadIdx.x >> 5);
    int lane = threadIdx.x & 31;
    const float* h = H + (size_t)row * RNND;
    float acc = 0.f;
    for (int k = lane; k < RNND; k += 32) acc = fmaf(h[k], sw[k], acc);
#pragma unroll
    for (int o = 16; o; o >>= 1) acc += __shfl_xor_sync(0xffffffffu, acc, o);
    if (lane == 0) {
        int t = row >> 6, b = row & 63;
        gout[b * TDEC + t] = 1.f / (1.f + __expf(-(acc + sb[0])));
    }
}

extern "C" void kernel_launch(void* const* d_in, const int* in_sizes, int n_in,
                              void* d_out, int out_size) {
    const float* enc  = (const float*)d_in[0];
    const float* mel  = (const float*)d_in[1];
    const float* W1   = (const float*)d_in[4];
    const float* b1   = (const float*)d_in[5];
    const float* W2   = (const float*)d_in[6];
    const float* b2   = (const float*)d_in[7];
    const float* Wq   = (const float*)d_in[8];
    const float* Wm   = (const float*)d_in[9];
    const float* av   = (const float*)d_in[10];
    const float* Wih  = (const float*)d_in[11];
    const float* Whh  = (const float*)d_in[12];
    const float* bih  = (const float*)d_in[13];
    const float* bhh  = (const float*)d_in[14];
    const float* melW = (const float*)d_in[15];
    const float* melb = (const float*)d_in[16];
    const float* stW  = (const float*)d_in[17];
    const float* stb  = (const float*)d_in[18];
    float* out = (float*)d_out;

    float *P1, *P2, *Q, *PM, *E, *X, *G1, *H;
    uint4 *AfHi, *AfLo, *BfIh, *WfHh, *BfSm, *WaHi, *WaLo, *BfPM;
    cudaGetSymbolAddress((void**)&P1,  g_P1);
    cudaGetSymbolAddress((void**)&P2,  g_P2);
    cudaGetSymbolAddress((void**)&Q,   g_Q);
    cudaGetSymbolAddress((void**)&PM,  g_PM);
    cudaGetSymbolAddress((void**)&E,   g_E);
    cudaGetSymbolAddress((void**)&X,   g_X);
    cudaGetSymbolAddress((void**)&G1,  g_G1);
    cudaGetSymbolAddress((void**)&H,   g_H);
    cudaGetSymbolAddress((void**)&AfHi, g_AfHi);
    cudaGetSymbolAddress((void**)&AfLo, g_AfLo);
    cudaGetSymbolAddress((void**)&BfIh, g_BfIh);
    cudaGetSymbolAddress((void**)&WfHh, g_WfHh);
    cudaGetSymbolAddress((void**)&BfSm, g_BfSm);
    cudaGetSymbolAddress((void**)&WaHi, g_WaHi);
    cudaGetSymbolAddress((void**)&WaLo, g_WaLo);
    cudaGetSymbolAddress((void**)&BfPM, g_BfPM);

    static int smem_set = 0;
    if (!smem_set) {
        cudaFuncSetAttribute(lstm_persistent_kernel,
                             cudaFuncAttributeMaxDynamicSharedMemorySize, 131072);
        smem_set = 1;
    }

    const int GSM = 49152;   // gemm_bf3 dynamic smem (2 stages x 24KB)

    zero_bar_kernel<<<1, 32>>>();

    // PM = enc @ Wm
    pack_afrag_kernel<<<(16*4608*32 + 255)/256, 256>>>(enc, 256, 16, 4608, AfHi, AfLo);
    pack_bfrag_kernel<<<(16*16*32 + 255)/256, 256>>>(Wm, BfSm, 16, 16, 128);
    gemm_bf3_kernel<<<dim3(1, 288, 1), 256, GSM>>>(AfHi, AfLo, BfSm, PM, 128,
        16, 16, 4608, nullptr, nullptr, 0, 0, 0, 0, 0);

    // prenet chain: Pin -> P1 -> P2 -> Q
    prep_pin_frag_kernel<<<(5*1024*32 + 255)/256, 256>>>(mel);
    pack_bfrag_kernel<<<(5*32*32 + 255)/256, 256>>>(W1, BfSm, 5, 32, 256);
    gemm_bf3_kernel<<<dim3(2, 64, 1), 256, GSM>>>(AfHi, AfLo, BfSm, P1, 256,
        5, 32, 1024, b1, nullptr, 1, 0, 0, 0, 0);
    pack_afrag_kernel<<<(16*1024*32 + 255)/256, 256>>>(P1, 256, 16, 1024, AfHi, AfLo);
    pack_bfrag_kernel<<<(16*32*32 + 255)/256, 256>>>(W2, BfSm, 16, 32, 256);
    gemm_bf3_kernel<<<dim3(2, 64, 1), 256, GSM>>>(AfHi, AfLo, BfSm, P2, 256,
        16, 32, 1024, b2, nullptr, 1, 0, 0, 0, 0);
    pack_afrag_kernel<<<(16*1024*32 + 255)/256, 256>>>(P2, 256, 16, 1024, AfHi, AfLo);
    pack_bfrag_kernel<<<(16*16*32 + 255)/256, 256>>>(Wq, BfSm, 16, 16, 128);
    gemm_bf3_kernel<<<dim3(1, 64, 1), 256, GSM>>>(AfHi, AfLo, BfSm, Q, 128,
        16, 16, 1024, nullptr, nullptr, 0, 0, 0, 0, 0);

    // attention
    att_e_kernel<<<dim3(TENC/64, BATCH), 256>>>(Q, PM, av, E);
    att_softmax_kernel<<<dim3(TDEC/8, BATCH), 256>>>(E, X, out + ALIGNS_OFF);

    // ctx = w @ PM per batch
    pack_w_kernel<<<dim3(144, 64), 256>>>(out + ALIGNS_OFF);
    pack_pm_kernel<<<dim3(144, 64), 256>>>(PM);
    gemm_bf3_kernel<<<dim3(1, 1, 64), 256, GSM>>>(WaHi, WaLo, BfPM, X, 64L * KX,
        72, 16, 16, nullptr, nullptr, 0, 0, 36864L, 36864L, (long)KX);

    // G1 = X @ Wih + b_ih + b_hh, written transposed [t][4096][64]
    pack_afrag_kernel<<<(80*1024*32 + 255)/256, 256>>>(X, KX, 80, 1024, AfHi, AfLo);
    pack_bfrag_kernel<<<(80*512*32 + 255)/256, 256>>>(Wih, BfIh, 80, 512, GATE4);
    gemm_bf3_kernel<<<dim3(32, 64, 1), 256, GSM>>>(AfHi, AfLo, BfIh, G1, GATE4,
        80, 512, 1024, bih, bhh, 0, 2, 0, 0, 0);

    // recurrence
    pack_bfrag_kernel<<<(64*512*32 + 255)/256, 256>>>(Whh, WfHh, 64, 512, GATE4);
    lstm_persistent_kernel<<<NBLK, 256, 131072>>>(G1, H);

    // outputs
    sgemm_kernel<<<dim3(1, ROWS/128), 256>>>(H, RNND, melW, MELD, out, MELD,
        ROWS, MELD, RNND, melb, 1);
    stop_kernel<<<ROWS/8, 256>>>(H, stW, stb, out + GATES_OFF);
}

// round 16
// speedup vs baseline: 1.0342x; 1.0342x over previous
#include <cuda_runtime.h>
#include <cuda_bf16.h>
#include <cuda_fp16.h>
#include <cstdint>
#include <cstddef>

#define BATCH 64
#define TDEC  256
#define TENC  1152
#define MELD  80
#define ATTD  128
#define RNND  1024
#define GATE4 4096
#define KX    1280
#define ROWS  16384

#define MELS_CNT   (BATCH*TDEC*MELD)
#define GATES_OFF  MELS_CNT
#define ALIGNS_OFF (MELS_CNT + BATCH*TDEC)

#define NBLK 128

// fp32 scratch
__device__ float g_P1 [ROWS * 256];
__device__ float g_P2 [ROWS * 256];
__device__ float g_Q  [ROWS * ATTD];
__device__ float g_PM [BATCH * TENC * ATTD];
__device__ float g_E  [(size_t)ROWS * TENC];
__device__ float g_X  [(size_t)ROWS * KX];
__device__ float g_G1 [(size_t)ROWS * GATE4];   // transposed: [t][4096][64]
__device__ float g_H  [(size_t)ROWS * RNND];
// fragment scratch (bf16 hi/lo)
__device__ uint4 g_AfHi[80 * 1024 * 32];
__device__ uint4 g_AfLo[80 * 1024 * 32];
__device__ uint4 g_BfIh[80 * 512 * 32];        // Wih frags; reused for melW frags
__device__ uint4 g_WfHh[64 * 512 * 32];
__device__ uint4 g_BfSm[16 * 32 * 32];
__device__ uint4 g_WaHi[64 * 72 * 16 * 32];
__device__ uint4 g_WaLo[64 * 72 * 16 * 32];
__device__ uint4 g_BfPM[64 * 72 * 16 * 32];
__device__ uint4 g_HfHi[2 * 64 * 4 * 32];
__device__ uint4 g_HfLo[2 * 64 * 4 * 32];
__device__ unsigned int g_bar;

// ---------- helpers ----------
__device__ __forceinline__ void mma16(float* c, uint32_t a0, uint32_t a1, uint32_t a2,
                                      uint32_t a3, uint32_t b0, uint32_t b1) {
    asm volatile(
        "mma.sync.aligned.m16n8k16.row.col.f32.bf16.bf16.f32 "
        "{%0,%1,%2,%3}, {%4,%5,%6,%7}, {%8,%9}, {%0,%1,%2,%3};\n"
        : "+f"(c[0]), "+f"(c[1]), "+f"(c[2]), "+f"(c[3])
        : "r"(a0), "r"(a1), "r"(a2), "r"(a3), "r"(b0), "r"(b1));
}

__device__ __forceinline__ void pack2(float e, float o, uint32_t& hi, uint32_t& lo) {
    __nv_bfloat16 eh = __float2bfloat16_rn(e);
    __nv_bfloat16 oh = __float2bfloat16_rn(o);
    __nv_bfloat16 el = __float2bfloat16_rn(e - __bfloat162float(eh));
    __nv_bfloat16 ol = __float2bfloat16_rn(o - __bfloat162float(oh));
    __nv_bfloat162 hv; hv.x = eh; hv.y = oh;
    __nv_bfloat162 lv; lv.x = el; lv.y = ol;
    hi = *reinterpret_cast<uint32_t*>(&hv);
    lo = *reinterpret_cast<uint32_t*>(&lv);
}

__device__ __forceinline__ float fast_tanh(float x) {
    return 1.f - __fdividef(2.f, __expf(2.f * x) + 1.f);
}

#define CP_ASYNC16(saddr, gptr) \
    asm volatile("cp.async.cg.shared.global [%0], [%1], 16;" \
                 :: "r"(saddr), "l"(gptr) : "memory")
#define CP_COMMIT() asm volatile("cp.async.commit_group;" ::: "memory")
#define CP_WAIT1()  asm volatile("cp.async.wait_group 1;" ::: "memory")

// ---------- prep/pack ----------
__global__ void zero_bar_kernel() { if (threadIdx.x == 0) g_bar = 0u; }

// ncols: real column count (cols >= ncols packed as zero)
__global__ void pack_bfrag_kernel(const float* __restrict__ W, uint4* __restrict__ out,
                                  int kbcnt, int nbcnt, int ldw, int ncols) {
    int i = blockIdx.x * blockDim.x + threadIdx.x;
    if (i < kbcnt * nbcnt * 32) {
        int lane = i & 31;
        int t32 = i >> 5;
        int nb = t32 % nbcnt;
        int kb = t32 / nbcnt;
        int q = lane & 3, gr = lane >> 2;
        int col = nb * 8 + gr;
        int k2a = kb * 8 + q, k2b = k2a + 4;
        float wa0 = 0.f, wa1 = 0.f, wb0 = 0.f, wb1 = 0.f;
        if (col < ncols) {
            wa0 = W[(size_t)(2 * k2a) * ldw + col];
            wa1 = W[(size_t)(2 * k2a + 1) * ldw + col];
            wb0 = W[(size_t)(2 * k2b) * ldw + col];
            wb1 = W[(size_t)(2 * k2b + 1) * ldw + col];
        }
        uint32_t h0, l0, h1, l1;
        pack2(wa0, wa1, h0, l0);
        pack2(wb0, wb1, h1, l1);
        out[i] = make_uint4(h0, h1, l0, l1);
    }
}

__global__ void pack_afrag_kernel(const float* __restrict__ A, int lda,
                                  int kbcnt, int mtcnt,
                                  uint4* __restrict__ outHi, uint4* __restrict__ outLo) {
    int i = blockIdx.x * blockDim.x + threadIdx.x;
    if (i < kbcnt * mtcnt * 32) {
        int lane = i & 31;
        int t32 = i >> 5;
        int mt = t32 % mtcnt;
        int kb = t32 / mtcnt;
        int q = lane & 3, gr = lane >> 2;
        int m0 = mt * 16 + gr, m1 = m0 + 8;
        int k2a = kb * 8 + q, k2b = k2a + 4;
        uint32_t h[4], l[4];
        pack2(A[(size_t)m0 * lda + 2 * k2a], A[(size_t)m0 * lda + 2 * k2a + 1], h[0], l[0]);
        pack2(A[(size_t)m1 * lda + 2 * k2a], A[(size_t)m1 * lda + 2 * k2a + 1], h[1], l[1]);
        pack2(A[(size_t)m0 * lda + 2 * k2b], A[(size_t)m0 * lda + 2 * k2b + 1], h[2], l[2]);
        pack2(A[(size_t)m1 * lda + 2 * k2b], A[(size_t)m1 * lda + 2 * k2b + 1], h[3], l[3]);
        outHi[i] = make_uint4(h[0], h[1], h[2], h[3]);
        outLo[i] = make_uint4(l[0], l[1], l[2], l[3]);
    }
}

__global__ void prep_pin_frag_kernel(const float* __restrict__ mel) {
    int i = blockIdx.x * blockDim.x + threadIdx.x;
    if (i < 5 * 1024 * 32) {
        int lane = i & 31;
        int t32 = i >> 5;
        int mt = t32 & 1023;
        int kb = t32 >> 10;
        int q = lane & 3, gr = lane >> 2;
        int k2a = kb * 8 + q, k2b = k2a + 4;
        uint32_t h[4], l[4];
#pragma unroll
        for (int half = 0; half < 2; half++) {
            int m = mt * 16 + gr + half * 8;
            int t = m >> 6, b = m & 63;
            const float* src = mel + ((size_t)b * TDEC + t) * MELD;
            float v0a = (t == 0) ? 0.f : src[2 * k2a];
            float v1a = (t == 0) ? 0.f : src[2 * k2a + 1];
            float v0b = (t == 0) ? 0.f : src[2 * k2b];
            float v1b = (t == 0) ? 0.f : src[2 * k2b + 1];
            pack2(v0a, v1a, h[half], l[half]);
            pack2(v0b, v1b, h[2 + half], l[2 + half]);
        }
        g_AfHi[i] = make_uint4(h[0], h[1], h[2], h[3]);
        g_AfLo[i] = make_uint4(l[0], l[1], l[2], l[3]);
    }
}

__global__ void pack_w_kernel(const float* __restrict__ aligns) {
    int z = blockIdx.y;
    int i = blockIdx.x * blockDim.x + threadIdx.x;
    int lane = i & 31;
    int t32 = i >> 5;
    int mt = t32 & 15;
    int kb = t32 >> 4;
    int q = lane & 3, gr = lane >> 2;
    int m0 = mt * 16 + gr, m1 = m0 + 8;
    int k2a = kb * 8 + q, k2b = k2a + 4;
    const float* A = aligns + (size_t)z * 256 * TENC;
    uint32_t h[4], l[4];
    pack2(A[(size_t)m0 * TENC + 2 * k2a], A[(size_t)m0 * TENC + 2 * k2a + 1], h[0], l[0]);
    pack2(A[(size_t)m1 * TENC + 2 * k2a], A[(size_t)m1 * TENC + 2 * k2a + 1], h[1], l[1]);
    pack2(A[(size_t)m0 * TENC + 2 * k2b], A[(size_t)m0 * TENC + 2 * k2b + 1], h[2], l[2]);
    pack2(A[(size_t)m1 * TENC + 2 * k2b], A[(size_t)m1 * TENC + 2 * k2b + 1], h[3], l[3]);
    size_t o = (size_t)z * 36864 + i;
    g_WaHi[o] = make_uint4(h[0], h[1], h[2], h[3]);
    g_WaLo[o] = make_uint4(l[0], l[1], l[2], l[3]);
}

__global__ void pack_pm_kernel(const float* __restrict__ PM) {
    int z = blockIdx.y;
    int i = blockIdx.x * blockDim.x + threadIdx.x;
    int lane = i & 31;
    int t32 = i >> 5;
    int nb = t32 & 15;
    int kb = t32 >> 4;
    int q = lane & 3, gr = lane >> 2;
    int col = nb * 8 + gr;
    int k2a = kb * 8 + q, k2b = k2a + 4;
    const float* W = PM + (size_t)z * TENC * ATTD;
    float wa0 = W[(size_t)(2 * k2a) * ATTD + col];
    float wa1 = W[(size_t)(2 * k2a + 1) * ATTD + col];
    float wb0 = W[(size_t)(2 * k2b) * ATTD + col];
    float wb1 = W[(size_t)(2 * k2b + 1) * ATTD + col];
    uint32_t h0, l0, h1, l1;
    pack2(wa0, wa1, h0, l0);
    pack2(wb0, wb1, h1, l1);
    g_BfPM[(size_t)z * 36864 + i] = make_uint4(h0, h1, l0, l1);
}

// ---------- bf16 hi/lo 3-term GEMM (R12 mainloop, direct __ldg) ----------
// Block = 256 rows x 128 cols. grid (ncols/128, M/256, nbatch).
// omode: 0 = C[row][col]; 1 = mel perm (orow=(r&63)*TDEC+(r>>6), col<MELD guard);
//        2 = G1-transpose
__global__ __launch_bounds__(256, 1) void gemm_bf3_kernel(
    const uint4* __restrict__ AfHi, const uint4* __restrict__ AfLo,
    const uint4* __restrict__ Bf, float* __restrict__ C, long ldc,
    int kbcnt, int nbcnt, int mtcnt,
    const float* __restrict__ bias1, const float* __restrict__ bias2,
    int relu, int omode, long aZoff, long bZoff, long cZoff)
{
    AfHi += (size_t)blockIdx.z * aZoff;
    AfLo += (size_t)blockIdx.z * aZoff;
    Bf   += (size_t)blockIdx.z * bZoff;
    C    += (size_t)blockIdx.z * cZoff;

    int tid = threadIdx.x;
    int warp = tid >> 5, lane = tid & 31;
    int wm = warp & 3, wn = warp >> 2;
    int gr = lane >> 2, q = lane & 3;
    int bm = blockIdx.y * 256, bn = blockIdx.x * 128;
    int mtBase = (bm >> 4) + wm * 4;
    int nbBase = (bn >> 3) + wn * 8;

    float acc[4][8][4];
#pragma unroll
    for (int i = 0; i < 4; i++)
#pragma unroll
        for (int j = 0; j < 8; j++)
#pragma unroll
            for (int r = 0; r < 4; r++) acc[i][j][r] = 0.f;

#pragma unroll 1
    for (int kb = 0; kb < kbcnt; kb++) {
        uint4 ah[4], al[4];
#pragma unroll
        for (int i = 0; i < 4; i++) {
            size_t aidx = ((size_t)kb * mtcnt + mtBase + i) * 32 + lane;
            ah[i] = __ldg(&AfHi[aidx]);
            al[i] = __ldg(&AfLo[aidx]);
        }
#pragma unroll
        for (int j = 0; j < 8; j++) {
            uint4 bv = __ldg(&Bf[((size_t)kb * nbcnt + nbBase + j) * 32 + lane]);
#pragma unroll
            for (int i = 0; i < 4; i++) {
                mma16(acc[i][j], ah[i].x, ah[i].y, ah[i].z, ah[i].w, bv.x, bv.y);
                mma16(acc[i][j], ah[i].x, ah[i].y, ah[i].z, ah[i].w, bv.z, bv.w);
                mma16(acc[i][j], al[i].x, al[i].y, al[i].z, al[i].w, bv.x, bv.y);
            }
        }
    }

#pragma unroll
    for (int i = 0; i < 4; i++) {
        int r0 = bm + (wm * 4 + i) * 16 + gr;
#pragma unroll
        for (int j = 0; j < 8; j++) {
            int c = bn + wn * 64 + j * 8 + 2 * q;
            float bb0 = 0.f, bb1 = 0.f;
            if (bias1) { bb0 += bias1[c]; bb1 += bias1[c + 1]; }
            if (bias2) { bb0 += bias2[c]; bb1 += bias2[c + 1]; }
            float v00 = acc[i][j][0] + bb0, v01 = acc[i][j][1] + bb1;
            float v10 = acc[i][j][2] + bb0, v11 = acc[i][j][3] + bb1;
            if (relu) {
                v00 = fmaxf(v00, 0.f); v01 = fmaxf(v01, 0.f);
                v10 = fmaxf(v10, 0.f); v11 = fmaxf(v11, 0.f);
            }
            int r1 = r0 + 8;
            if (omode == 2) {
                size_t o00 = ((size_t)(r0 >> 6) * GATE4 + c) * 64 + (r0 & 63);
                size_t o10 = ((size_t)(r1 >> 6) * GATE4 + c) * 64 + (r1 & 63);
                C[o00]      = v00;
                C[o00 + 64] = v01;
                C[o10]      = v10;
                C[o10 + 64] = v11;
            } else if (omode == 1) {
                if (c < MELD) {
                    size_t or0 = (size_t)(r0 & 63) * TDEC + (r0 >> 6);
                    size_t or1 = (size_t)(r1 & 63) * TDEC + (r1 >> 6);
                    C[or0 * MELD + c]     = v00;
                    C[or0 * MELD + c + 1] = v01;
                    C[or1 * MELD + c]     = v10;
                    C[or1 * MELD + c + 1] = v11;
                }
            } else {
                C[(size_t)r0 * ldc + c]     = v00;
                C[(size_t)r0 * ldc + c + 1] = v01;
                C[(size_t)r1 * ldc + c]     = v10;
                C[(size_t)r1 * ldc + c + 1] = v11;
            }
        }
    }
}

// ---------- G1-only GEMM: 3-stage cp.async, ONE barrier per kb ----------
// Same 256x128 tile. Epilogue hardcoded omode=2 (G1 transpose) + bias1+bias2.
__global__ __launch_bounds__(256, 1) void gemm_pipe_kernel(
    const uint4* __restrict__ AfHi, const uint4* __restrict__ AfLo,
    const uint4* __restrict__ Bf, float* __restrict__ C,
    int kbcnt, int nbcnt, int mtcnt,
    const float* __restrict__ bias1, const float* __restrict__ bias2)
{
    extern __shared__ uint4 sm[];   // 3 * 1536 uint4 = 72 KB
    int tid = threadIdx.x;
    int warp = tid >> 5, lane = tid & 31;
    int wm = warp & 3, wn = warp >> 2;
    int gr = lane >> 2, q = lane & 3;
    int bm = blockIdx.y * 256, bn = blockIdx.x * 128;
    int mtBase0 = bm >> 4;
    int nbBase0 = bn >> 3;

    uint32_t smem_u32 = (uint32_t)__cvta_generic_to_shared(sm);

    float acc[4][8][4];
#pragma unroll
    for (int i = 0; i < 4; i++)
#pragma unroll
        for (int j = 0; j < 8; j++)
#pragma unroll
            for (int r = 0; r < 4; r++) acc[i][j][r] = 0.f;

    auto issue_stage = [&](int kb, int s) {
        uint32_t sb = smem_u32 + (uint32_t)s * 1536u * 16u;
#pragma unroll
        for (int p = 0; p < 6; p++) {
            int e = tid + p * 256;
            const uint4* src;
            if (e < 512)
                src = &AfHi[((size_t)kb * mtcnt + mtBase0 + (e >> 5)) * 32 + (e & 31)];
            else if (e < 1024)
                src = &AfLo[((size_t)kb * mtcnt + mtBase0 + ((e - 512) >> 5)) * 32 + (e & 31)];
            else
                src = &Bf[((size_t)kb * nbcnt + nbBase0 + ((e - 1024) >> 5)) * 32 + (e & 31)];
            CP_ASYNC16(sb + (uint32_t)e * 16u, src);
        }
    };

    issue_stage(0, 0);
    CP_COMMIT();
    issue_stage(1, 1);
    CP_COMMIT();

    for (int kb = 0; kb < kbcnt; kb++) {
        CP_WAIT1();          // my group for stage kb is complete
        __syncthreads();     // all threads waited -> stage kb globally visible;
                             // all threads finished consuming kb-1 -> safe to reuse its buffer
        if (kb + 2 < kbcnt) issue_stage(kb + 2, (kb + 2) % 3);
        CP_COMMIT();

        const uint4* sBase = sm + (size_t)(kb % 3) * 1536;
        uint4 ah[4], al[4];
#pragma unroll
        for (int i = 0; i < 4; i++) {
            ah[i] = sBase[(wm * 4 + i) * 32 + lane];
            al[i] = sBase[512 + (wm * 4 + i) * 32 + lane];
        }
#pragma unroll
        for (int j = 0; j < 8; j++) {
            uint4 bv = sBase[1024 + (wn * 8 + j) * 32 + lane];
#pragma unroll
            for (int i = 0; i < 4; i++) {
                mma16(acc[i][j], ah[i].x, ah[i].y, ah[i].z, ah[i].w, bv.x, bv.y);
                mma16(acc[i][j], ah[i].x, ah[i].y, ah[i].z, ah[i].w, bv.z, bv.w);
                mma16(acc[i][j], al[i].x, al[i].y, al[i].z, al[i].w, bv.x, bv.y);
            }
        }
    }

#pragma unroll
    for (int i = 0; i < 4; i++) {
        int r0 = bm + (wm * 4 + i) * 16 + gr;
#pragma unroll
        for (int j = 0; j < 8; j++) {
            int c = bn + wn * 64 + j * 8 + 2 * q;
            float bb0 = bias1[c] + bias2[c];
            float bb1 = bias1[c + 1] + bias2[c + 1];
            int r1 = r0 + 8;
            size_t o00 = ((size_t)(r0 >> 6) * GATE4 + c) * 64 + (r0 & 63);
            size_t o10 = ((size_t)(r1 >> 6) * GATE4 + c) * 64 + (r1 & 63);
            C[o00]      = acc[i][j][0] + bb0;
            C[o00 + 64] = acc[i][j][1] + bb1;
            C[o10]      = acc[i][j][2] + bb0;
            C[o10 + 64] = acc[i][j][3] + bb1;
        }
    }
}

// ---------- attention: logits via f16x2 tanh ----------
__global__ __launch_bounds__(256) void att_e_kernel(
    const float* __restrict__ Q, const float* __restrict__ PM,
    const float* __restrict__ v, float* __restrict__ E)
{
    __shared__ __half2 pm_s[64][65];
    __shared__ __half2 qs[4][64];
    __shared__ float v_s[128];
    int b = blockIdx.y, te0 = blockIdx.x * 64, tid = threadIdx.x;
    if (tid < 128) v_s[tid] = v[tid];
    for (int i = tid; i < 64 * 64; i += 256) {
        int r = i >> 6, c2 = i & 63;
        float2 f = *reinterpret_cast<const float2*>(
            PM + ((size_t)b * TENC + te0 + r) * ATTD + 2 * c2);
        pm_s[r][c2] = __floats2half2_rn(f.x, f.y);
    }
    int te = tid & 63, qq = tid >> 6;
    __syncthreads();
    for (int t0 = 0; t0 < TDEC; t0 += 4) {
        {
            int q = tid >> 6, c2 = tid & 63;
            float2 f = *reinterpret_cast<const float2*>(
                Q + ((size_t)(t0 + q) * 64 + b) * ATTD + 2 * c2);
            qs[q][c2] = __floats2half2_rn(f.x, f.y);
        }
        __syncthreads();
        float e = 0.f;
#pragma unroll 4
        for (int d2 = 0; d2 < 64; d2++) {
            __half2 x2 = __hadd2(qs[qq][d2], pm_s[te][d2]);
            uint32_t xi = *reinterpret_cast<uint32_t*>(&x2);
            uint32_t ti;
            asm("tanh.approx.f16x2 %0, %1;" : "=r"(ti) : "r"(xi));
            __half2 t2 = *reinterpret_cast<__half2*>(&ti);
            float2 tf = __half22float2(t2);
            e = fmaf(v_s[2 * d2], tf.x, e);
            e = fmaf(v_s[2 * d2 + 1], tf.y, e);
        }
        E[((size_t)(t0 + qq) * 64 + b) * TENC + te0 + te] = e;
        __syncthreads();
    }
}

__global__ __launch_bounds__(256) void att_softmax_kernel(
    const float* __restrict__ E, float* __restrict__ X, float* __restrict__ aligns)
{
    __shared__ float w_s[8][TENC];
    __shared__ float inv_s[8];
    int b = blockIdx.y, t0 = blockIdx.x * 8, tid = threadIdx.x;
    int warp = tid >> 5, lane = tid & 31;
    {
        int t = t0 + warp;
        size_t eb = ((size_t)t * 64 + b) * TENC;
        float m = -1e30f;
        for (int te = lane; te < TENC; te += 32) m = fmaxf(m, E[eb + te]);
#pragma unroll
        for (int o = 16; o; o >>= 1) m = fmaxf(m, __shfl_xor_sync(0xffffffffu, m, o));
        float s = 0.f;
        for (int te = lane; te < TENC; te += 32) {
            float w = __expf(E[eb + te] - m);
            w_s[warp][te] = w; s += w;
        }
#pragma unroll
        for (int o = 16; o; o >>= 1) s += __shfl_xor_sync(0xffffffffu, s, o);
        if (lane == 0) inv_s[warp] = 1.f / s;
    }
    __syncthreads();
    for (int i = tid; i < 8 * TENC; i += 256) {
        int q = i / TENC, te = i - q * TENC;
        float wv = w_s[q][te] * inv_s[q];
        int t = t0 + q;
        aligns[((size_t)b * TDEC + t) * TENC + te] = wv;
        X[((size_t)t * 64 + b) * KX + ATTD + te] = wv;
    }
}

// ---------- persistent LSTM: kb-split warps (R12 structure) ----------
__global__ __launch_bounds__(256, 1) void lstm_persistent_kernel(
    const float* __restrict__ G1, float* __restrict__ H)
{
    extern __shared__ uint4 smW[];
    __shared__ float st2[2][64][36];

    int tid = threadIdx.x;
    int warp = tid >> 5, lane = tid & 31;
    int gr = lane >> 2, q = lane & 3;
    int rt = warp & 3, kh = warp >> 2;
    int u0 = blockIdx.x * 8;
    int base = u0 >> 3;

    for (int i = tid; i < 64 * 4 * 32; i += 256) {
        int lane2 = i & 31, gate = (i >> 5) & 3, kb = i >> 7;
        smW[i] = __ldg(&g_WfHh[((size_t)kb * 512 + gate * 128 + base) * 32 + lane2]);
    }
    __syncthreads();

    int pb = tid & 63, pq = tid >> 6;
    float creg[2] = {0.f, 0.f};

    int p = (u0 >> 1) + pq;
    int kbW = p >> 3, qq = p & 7;
    int rtW = pb >> 4, rin = pb & 15;
    int comp = (qq < 4) ? ((rin < 8) ? 0 : 1) : ((rin < 8) ? 2 : 3);
    int laneW = (rin & 7) * 4 + (qq & 3);
    int fragIdx = ((kbW * 4 + rtW) * 32 + laneW) * 4 + comp;

    int kbeg = kh * 32;

    for (int t = 0; t < TDEC; t++) {
        float g1p[2][4];
        {
            size_t gb = (size_t)t * GATE4 * 64;
#pragma unroll
            for (int s = 0; s < 2; s++) {
                int u = u0 + 2 * pq + s;
                g1p[s][0] = __ldg(G1 + gb + (size_t)(0 * RNND + u) * 64 + pb);
                g1p[s][1] = __ldg(G1 + gb + (size_t)(1 * RNND + u) * 64 + pb);
                g1p[s][2] = __ldg(G1 + gb + (size_t)(2 * RNND + u) * 64 + pb);
                g1p[s][3] = __ldg(G1 + gb + (size_t)(3 * RNND + u) * 64 + pb);
            }
        }

        float acc[4][4];
#pragma unroll
        for (int g = 0; g < 4; g++)
#pragma unroll
            for (int r = 0; r < 4; r++) acc[g][r] = 0.f;

        if (t > 0) {
            int bufR = (t - 1) & 1;
            const uint4* AH = g_HfHi + (size_t)bufR * 64 * 4 * 32;
            const uint4* AL = g_HfLo + (size_t)bufR * 64 * 4 * 32;
#pragma unroll 8
            for (int kk = 0; kk < 32; kk++) {
                int kb = kbeg + kk;
                uint4 ah = __ldcg(AH + (kb * 4 + rt) * 32 + lane);
                uint4 al = __ldcg(AL + (kb * 4 + rt) * 32 + lane);
#pragma unroll
                for (int g = 0; g < 4; g++) {
                    uint4 b = smW[kb * 128 + g * 32 + lane];
                    mma16(acc[g], ah.x, ah.y, ah.z, ah.w, b.x, b.y);
                    mma16(acc[g], ah.x, ah.y, ah.z, ah.w, b.z, b.w);
                    mma16(acc[g], al.x, al.y, al.z, al.w, b.x, b.y);
                }
            }
        }

#pragma unroll
        for (int g = 0; g < 4; g++) {
            int c = g * 8 + 2 * q;
            int r0 = rt * 16 + gr;
            st2[kh][r0][c]         = acc[g][0];
            st2[kh][r0][c + 1]     = acc[g][1];
            st2[kh][r0 + 8][c]     = acc[g][2];
            st2[kh][r0 + 8][c + 1] = acc[g][3];
        }
        __syncthreads();

        float hpair[2];
#pragma unroll
        for (int s = 0; s < 2; s++) {
            int ul = 2 * pq + s;
            int u = u0 + ul;
            float gi = st2[0][pb][ul]      + st2[1][pb][ul]      + g1p[s][0];
            float gf = st2[0][pb][8 + ul]  + st2[1][pb][8 + ul]  + g1p[s][1];
            float gg = st2[0][pb][16 + ul] + st2[1][pb][16 + ul] + g1p[s][2];
            float go = st2[0][pb][24 + ul] + st2[1][pb][24 + ul] + g1p[s][3];
            float i_ = 1.f / (1.f + __expf(-gi));
            float f_ = 1.f / (1.f + __expf(-gf));
            float g_ = fast_tanh(gg);
            float o_ = 1.f / (1.f + __expf(-go));
            float cn = f_ * creg[s] + i_ * g_;
            creg[s] = cn;
            float hn = o_ * fast_tanh(cn);
            hpair[s] = hn;
            H[((size_t)t * 64 + pb) * RNND + u] = hn;
        }
        {
            int bufW = t & 1;
            uint32_t hi, lo;
            pack2(hpair[0], hpair[1], hi, lo);
            size_t off = (size_t)bufW * 64 * 4 * 32 * 4 + fragIdx;
            reinterpret_cast<uint32_t*>(g_HfHi)[off] = hi;
            reinterpret_cast<uint32_t*>(g_HfLo)[off] = lo;
        }
        __syncthreads();
        if (tid == 0) {
            asm volatile("red.release.gpu.global.add.u32 [%0], %1;"
                         :: "l"(&g_bar), "r"(1u) : "memory");
            unsigned tgt = (unsigned)NBLK * (unsigned)(t + 1);
            unsigned v;
            do {
                asm volatile("ld.global.acquire.gpu.u32 %0, [%1];" : "=r"(v) : "l"(&g_bar));
            } while (v < tgt);
        }
        __syncthreads();
    }
}

__global__ __launch_bounds__(256) void stop_kernel(
    const float* __restrict__ H, const float* __restrict__ sw,
    const float* __restrict__ sb, float* __restrict__ gout)
{
    int row = blockIdx.x * 8 + (threadIdx.x >> 5);
    int lane = threadIdx.x & 31;
    const float* h = H + (size_t)row * RNND;
    float acc = 0.f;
    for (int k = lane; k < RNND; k += 32) acc = fmaf(h[k], sw[k], acc);
#pragma unroll
    for (int o = 16; o; o >>= 1) acc += __shfl_xor_sync(0xffffffffu, acc, o);
    if (lane == 0) {
        int t = row >> 6, b = row & 63;
        gout[b * TDEC + t] = 1.f / (1.f + __expf(-(acc + sb[0])));
    }
}

extern "C" void kernel_launch(void* const* d_in, const int* in_sizes, int n_in,
                              void* d_out, int out_size) {
    const float* enc  = (const float*)d_in[0];
    const float* mel  = (const float*)d_in[1];
    const float* W1   = (const float*)d_in[4];
    const float* b1   = (const float*)d_in[5];
    const float* W2   = (const float*)d_in[6];
    const float* b2   = (const float*)d_in[7];
    const float* Wq   = (const float*)d_in[8];
    const float* Wm   = (const float*)d_in[9];
    const float* av   = (const float*)d_in[10];
    const float* Wih  = (const float*)d_in[11];
    const float* Whh  = (const float*)d_in[12];
    const float* bih  = (const float*)d_in[13];
    const float* bhh  = (const float*)d_in[14];
    const float* melW = (const float*)d_in[15];
    const float* melb = (const float*)d_in[16];
    const float* stW  = (const float*)d_in[17];
    const float* stb  = (const float*)d_in[18];
    float* out = (float*)d_out;

    float *P1, *P2, *Q, *PM, *E, *X, *G1, *H;
    uint4 *AfHi, *AfLo, *BfIh, *WfHh, *BfSm, *WaHi, *WaLo, *BfPM;
    cudaGetSymbolAddress((void**)&P1,  g_P1);
    cudaGetSymbolAddress((void**)&P2,  g_P2);
    cudaGetSymbolAddress((void**)&Q,   g_Q);
    cudaGetSymbolAddress((void**)&PM,  g_PM);
    cudaGetSymbolAddress((void**)&E,   g_E);
    cudaGetSymbolAddress((void**)&X,   g_X);
    cudaGetSymbolAddress((void**)&G1,  g_G1);
    cudaGetSymbolAddress((void**)&H,   g_H);
    cudaGetSymbolAddress((void**)&AfHi, g_AfHi);
    cudaGetSymbolAddress((void**)&AfLo, g_AfLo);
    cudaGetSymbolAddress((void**)&BfIh, g_BfIh);
    cudaGetSymbolAddress((void**)&WfHh, g_WfHh);
    cudaGetSymbolAddress((void**)&BfSm, g_BfSm);
    cudaGetSymbolAddress((void**)&WaHi, g_WaHi);
    cudaGetSymbolAddress((void**)&WaLo, g_WaLo);
    cudaGetSymbolAddress((void**)&BfPM, g_BfPM);

    static int attr_set = 0;
    if (!attr_set) {
        cudaFuncSetAttribute(lstm_persistent_kernel,
                             cudaFuncAttributeMaxDynamicSharedMemorySize, 131072);
        cudaFuncSetAttribute(gemm_pipe_kernel,
                             cudaFuncAttributeMaxDynamicSharedMemorySize, 73728);
        attr_set = 1;
    }

    zero_bar_kernel<<<1, 32>>>();

    // PM = enc @ Wm
    pack_afrag_kernel<<<(16*4608*32 + 255)/256, 256>>>(enc, 256, 16, 4608, AfHi, AfLo);
    pack_bfrag_kernel<<<(16*16*32 + 255)/256, 256>>>(Wm, BfSm, 16, 16, 128, 128);
    gemm_bf3_kernel<<<dim3(1, 288, 1), 256>>>(AfHi, AfLo, BfSm, PM, 128,
        16, 16, 4608, nullptr, nullptr, 0, 0, 0, 0, 0);

    // prenet chain: Pin -> P1 -> P2 -> Q
    prep_pin_frag_kernel<<<(5*1024*32 + 255)/256, 256>>>(mel);
    pack_bfrag_kernel<<<(5*32*32 + 255)/256, 256>>>(W1, BfSm, 5, 32, 256, 256);
    gemm_bf3_kernel<<<dim3(2, 64, 1), 256>>>(AfHi, AfLo, BfSm, P1, 256,
        5, 32, 1024, b1, nullptr, 1, 0, 0, 0, 0);
    pack_afrag_kernel<<<(16*1024*32 + 255)/256, 256>>>(P1, 256, 16, 1024, AfHi, AfLo);
    pack_bfrag_kernel<<<(16*32*32 + 255)/256, 256>>>(W2, BfSm, 16, 32, 256, 256);
    gemm_bf3_kernel<<<dim3(2, 64, 1), 256>>>(AfHi, AfLo, BfSm, P2, 256,
        16, 32, 1024, b2, nullptr, 1, 0, 0, 0, 0);
    pack_afrag_kernel<<<(16*1024*32 + 255)/256, 256>>>(P2, 256, 16, 1024, AfHi, AfLo);
    pack_bfrag_kernel<<<(16*16*32 + 255)/256, 256>>>(Wq, BfSm, 16, 16, 128, 128);
    gemm_bf3_kernel<<<dim3(1, 64, 1), 256>>>(AfHi, AfLo, BfSm, Q, 128,
        16, 16, 1024, nullptr, nullptr, 0, 0, 0, 0, 0);

    // attention
    att_e_kernel<<<dim3(TENC/64, BATCH), 256>>>(Q, PM, av, E);
    att_softmax_kernel<<<dim3(TDEC/8, BATCH), 256>>>(E, X, out + ALIGNS_OFF);

    // ctx = w @ PM per batch
    pack_w_kernel<<<dim3(144, 64), 256>>>(out + ALIGNS_OFF);
    pack_pm_kernel<<<dim3(144, 64), 256>>>(PM);
    gemm_bf3_kernel<<<dim3(1, 1, 64), 256>>>(WaHi, WaLo, BfPM, X, 64L * KX,
        72, 16, 16, nullptr, nullptr, 0, 0, 36864L, 36864L, (long)KX);

    // G1 = X @ Wih + b_ih + b_hh, transposed output, pipelined gemm
    pack_afrag_kernel<<<(80*1024*32 + 255)/256, 256>>>(X, KX, 80, 1024, AfHi, AfLo);
    pack_bfrag_kernel<<<(80*512*32 + 255)/256, 256>>>(Wih, BfIh, 80, 512, GATE4, GATE4);
    gemm_pipe_kernel<<<dim3(32, 64, 1), 256, 73728>>>(AfHi, AfLo, BfIh, G1,
        80, 512, 1024, bih, bhh);

    // recurrence
    pack_bfrag_kernel<<<(64*512*32 + 255)/256, 256>>>(Whh, WfHh, 64, 512, GATE4, GATE4);
    lstm_persistent_kernel<<<NBLK, 256, 131072>>>(G1, H);

    // mels = H @ melW + melb (tensor path, rowperm epilogue); melW frags reuse BfIh
    pack_afrag_kernel<<<(64*1024*32 + 255)/256, 256>>>(H, RNND, 64, 1024, AfHi, AfLo);
    pack_bfrag_kernel<<<(64*16*32 + 255)/256, 256>>>(melW, BfIh, 64, 16, MELD, MELD);
    gemm_bf3_kernel<<<dim3(1, 64, 1), 256>>>(AfHi, AfLo, BfIh, out, MELD,
        64, 16, 1024, melb, nullptr, 0, 1, 0, 0, 0);

    stop_kernel<<<ROWS/8, 256>>>(H, stW, stb, out + GATES_OFF);
}

// round 17
// speedup vs baseline: 1.0660x; 1.0308x over previous
#include <cuda_runtime.h>
#include <cuda_bf16.h>
#include <cuda_fp16.h>
#include <cstdint>
#include <cstddef>

#define BATCH 64
#define TDEC  256
#define TENC  1152
#define MELD  80
#define ATTD  128
#define RNND  1024
#define GATE4 4096
#define KX    1280
#define ROWS  16384

#define MELS_CNT   (BATCH*TDEC*MELD)
#define GATES_OFF  MELS_CNT
#define ALIGNS_OFF (MELS_CNT + BATCH*TDEC)

#define NBLK 128

// fp32 scratch
__device__ float g_P1 [ROWS * 256];
__device__ float g_P2 [ROWS * 256];
__device__ float g_Q  [ROWS * ATTD];
__device__ float g_PM [BATCH * TENC * ATTD];
__device__ float g_E  [(size_t)ROWS * TENC];
__device__ float g_X  [(size_t)ROWS * KX];
__device__ float g_G1 [(size_t)ROWS * GATE4];   // transposed: [t][4096][64]
__device__ float g_H  [(size_t)ROWS * RNND];
// fragment scratch (bf16 hi/lo)
__device__ uint4 g_AfHi[80 * 1024 * 32];
__device__ uint4 g_AfLo[80 * 1024 * 32];
__device__ uint4 g_BfIh[80 * 512 * 32];        // Wih frags; reused for melW frags
__device__ uint4 g_WfHh[64 * 512 * 32];
__device__ uint4 g_BfSm[16 * 32 * 32];
__device__ uint4 g_WaHi[64 * 72 * 16 * 32];
__device__ uint4 g_WaLo[64 * 72 * 16 * 32];
__device__ uint4 g_BfPM[64 * 72 * 16 * 32];
__device__ uint4 g_HfHi[2 * 64 * 4 * 32];
__device__ uint4 g_HfLo[2 * 64 * 4 * 32];
__device__ unsigned int g_bar;

// ---------- helpers ----------
__device__ __forceinline__ void mma16(float* c, uint32_t a0, uint32_t a1, uint32_t a2,
                                      uint32_t a3, uint32_t b0, uint32_t b1) {
    asm volatile(
        "mma.sync.aligned.m16n8k16.row.col.f32.bf16.bf16.f32 "
        "{%0,%1,%2,%3}, {%4,%5,%6,%7}, {%8,%9}, {%0,%1,%2,%3};\n"
        : "+f"(c[0]), "+f"(c[1]), "+f"(c[2]), "+f"(c[3])
        : "r"(a0), "r"(a1), "r"(a2), "r"(a3), "r"(b0), "r"(b1));
}

__device__ __forceinline__ void pack2(float e, float o, uint32_t& hi, uint32_t& lo) {
    __nv_bfloat16 eh = __float2bfloat16_rn(e);
    __nv_bfloat16 oh = __float2bfloat16_rn(o);
    __nv_bfloat16 el = __float2bfloat16_rn(e - __bfloat162float(eh));
    __nv_bfloat16 ol = __float2bfloat16_rn(o - __bfloat162float(oh));
    __nv_bfloat162 hv; hv.x = eh; hv.y = oh;
    __nv_bfloat162 lv; lv.x = el; lv.y = ol;
    hi = *reinterpret_cast<uint32_t*>(&hv);
    lo = *reinterpret_cast<uint32_t*>(&lv);
}

__device__ __forceinline__ float fast_tanh(float x) {
    return 1.f - __fdividef(2.f, __expf(2.f * x) + 1.f);
}

// ---------- prep/pack ----------
__global__ void zero_bar_kernel() { if (threadIdx.x == 0) g_bar = 0u; }

// ncols: real column count (cols >= ncols packed as zero)
__global__ void pack_bfrag_kernel(const float* __restrict__ W, uint4* __restrict__ out,
                                  int kbcnt, int nbcnt, int ldw, int ncols) {
    int i = blockIdx.x * blockDim.x + threadIdx.x;
    if (i < kbcnt * nbcnt * 32) {
        int lane = i & 31;
        int t32 = i >> 5;
        int nb = t32 % nbcnt;
        int kb = t32 / nbcnt;
        int q = lane & 3, gr = lane >> 2;
        int col = nb * 8 + gr;
        int k2a = kb * 8 + q, k2b = k2a + 4;
        float wa0 = 0.f, wa1 = 0.f, wb0 = 0.f, wb1 = 0.f;
        if (col < ncols) {
            wa0 = W[(size_t)(2 * k2a) * ldw + col];
            wa1 = W[(size_t)(2 * k2a + 1) * ldw + col];
            wb0 = W[(size_t)(2 * k2b) * ldw + col];
            wb1 = W[(size_t)(2 * k2b + 1) * ldw + col];
        }
        uint32_t h0, l0, h1, l1;
        pack2(wa0, wa1, h0, l0);
        pack2(wb0, wb1, h1, l1);
        out[i] = make_uint4(h0, h1, l0, l1);
    }
}

__global__ void pack_afrag_kernel(const float* __restrict__ A, int lda,
                                  int kbcnt, int mtcnt,
                                  uint4* __restrict__ outHi, uint4* __restrict__ outLo) {
    int i = blockIdx.x * blockDim.x + threadIdx.x;
    if (i < kbcnt * mtcnt * 32) {
        int lane = i & 31;
        int t32 = i >> 5;
        int mt = t32 % mtcnt;
        int kb = t32 / mtcnt;
        int q = lane & 3, gr = lane >> 2;
        int m0 = mt * 16 + gr, m1 = m0 + 8;
        int k2a = kb * 8 + q, k2b = k2a + 4;
        uint32_t h[4], l[4];
        pack2(A[(size_t)m0 * lda + 2 * k2a], A[(size_t)m0 * lda + 2 * k2a + 1], h[0], l[0]);
        pack2(A[(size_t)m1 * lda + 2 * k2a], A[(size_t)m1 * lda + 2 * k2a + 1], h[1], l[1]);
        pack2(A[(size_t)m0 * lda + 2 * k2b], A[(size_t)m0 * lda + 2 * k2b + 1], h[2], l[2]);
        pack2(A[(size_t)m1 * lda + 2 * k2b], A[(size_t)m1 * lda + 2 * k2b + 1], h[3], l[3]);
        outHi[i] = make_uint4(h[0], h[1], h[2], h[3]);
        outLo[i] = make_uint4(l[0], l[1], l[2], l[3]);
    }
}

__global__ void prep_pin_frag_kernel(const float* __restrict__ mel) {
    int i = blockIdx.x * blockDim.x + threadIdx.x;
    if (i < 5 * 1024 * 32) {
        int lane = i & 31;
        int t32 = i >> 5;
        int mt = t32 & 1023;
        int kb = t32 >> 10;
        int q = lane & 3, gr = lane >> 2;
        int k2a = kb * 8 + q, k2b = k2a + 4;
        uint32_t h[4], l[4];
#pragma unroll
        for (int half = 0; half < 2; half++) {
            int m = mt * 16 + gr + half * 8;
            int t = m >> 6, b = m & 63;
            const float* src = mel + ((size_t)b * TDEC + t) * MELD;
            float v0a = (t == 0) ? 0.f : src[2 * k2a];
            float v1a = (t == 0) ? 0.f : src[2 * k2a + 1];
            float v0b = (t == 0) ? 0.f : src[2 * k2b];
            float v1b = (t == 0) ? 0.f : src[2 * k2b + 1];
            pack2(v0a, v1a, h[half], l[half]);
            pack2(v0b, v1b, h[2 + half], l[2 + half]);
        }
        g_AfHi[i] = make_uint4(h[0], h[1], h[2], h[3]);
        g_AfLo[i] = make_uint4(l[0], l[1], l[2], l[3]);
    }
}

__global__ void pack_w_kernel(const float* __restrict__ aligns) {
    int z = blockIdx.y;
    int i = blockIdx.x * blockDim.x + threadIdx.x;
    int lane = i & 31;
    int t32 = i >> 5;
    int mt = t32 & 15;
    int kb = t32 >> 4;
    int q = lane & 3, gr = lane >> 2;
    int m0 = mt * 16 + gr, m1 = m0 + 8;
    int k2a = kb * 8 + q, k2b = k2a + 4;
    const float* A = aligns + (size_t)z * 256 * TENC;
    uint32_t h[4], l[4];
    pack2(A[(size_t)m0 * TENC + 2 * k2a], A[(size_t)m0 * TENC + 2 * k2a + 1], h[0], l[0]);
    pack2(A[(size_t)m1 * TENC + 2 * k2a], A[(size_t)m1 * TENC + 2 * k2a + 1], h[1], l[1]);
    pack2(A[(size_t)m0 * TENC + 2 * k2b], A[(size_t)m0 * TENC + 2 * k2b + 1], h[2], l[2]);
    pack2(A[(size_t)m1 * TENC + 2 * k2b], A[(size_t)m1 * TENC + 2 * k2b + 1], h[3], l[3]);
    size_t o = (size_t)z * 36864 + i;
    g_WaHi[o] = make_uint4(h[0], h[1], h[2], h[3]);
    g_WaLo[o] = make_uint4(l[0], l[1], l[2], l[3]);
}

__global__ void pack_pm_kernel(const float* __restrict__ PM) {
    int z = blockIdx.y;
    int i = blockIdx.x * blockDim.x + threadIdx.x;
    int lane = i & 31;
    int t32 = i >> 5;
    int nb = t32 & 15;
    int kb = t32 >> 4;
    int q = lane & 3, gr = lane >> 2;
    int col = nb * 8 + gr;
    int k2a = kb * 8 + q, k2b = k2a + 4;
    const float* W = PM + (size_t)z * TENC * ATTD;
    float wa0 = W[(size_t)(2 * k2a) * ATTD + col];
    float wa1 = W[(size_t)(2 * k2a + 1) * ATTD + col];
    float wb0 = W[(size_t)(2 * k2b) * ATTD + col];
    float wb1 = W[(size_t)(2 * k2b + 1) * ATTD + col];
    uint32_t h0, l0, h1, l1;
    pack2(wa0, wa1, h0, l0);
    pack2(wb0, wb1, h1, l1);
    g_BfPM[(size_t)z * 36864 + i] = make_uint4(h0, h1, l0, l1);
}

// ---------- bf16 hi/lo 3-term GEMM (R12 mainloop, direct __ldg) ----------
// Block = 256 rows x 128 cols. grid (ncols/128, M/256, nbatch).
// omode: 0 = C[row][col]; 1 = mel perm; 2 = G1-transpose
__global__ __launch_bounds__(256, 1) void gemm_bf3_kernel(
    const uint4* __restrict__ AfHi, const uint4* __restrict__ AfLo,
    const uint4* __restrict__ Bf, float* __restrict__ C, long ldc,
    int kbcnt, int nbcnt, int mtcnt,
    const float* __restrict__ bias1, const float* __restrict__ bias2,
    int relu, int omode, long aZoff, long bZoff, long cZoff)
{
    AfHi += (size_t)blockIdx.z * aZoff;
    AfLo += (size_t)blockIdx.z * aZoff;
    Bf   += (size_t)blockIdx.z * bZoff;
    C    += (size_t)blockIdx.z * cZoff;

    int tid = threadIdx.x;
    int warp = tid >> 5, lane = tid & 31;
    int wm = warp & 3, wn = warp >> 2;
    int gr = lane >> 2, q = lane & 3;
    int bm = blockIdx.y * 256, bn = blockIdx.x * 128;
    int mtBase = (bm >> 4) + wm * 4;
    int nbBase = (bn >> 3) + wn * 8;

    float acc[4][8][4];
#pragma unroll
    for (int i = 0; i < 4; i++)
#pragma unroll
        for (int j = 0; j < 8; j++)
#pragma unroll
            for (int r = 0; r < 4; r++) acc[i][j][r] = 0.f;

#pragma unroll 1
    for (int kb = 0; kb < kbcnt; kb++) {
        uint4 ah[4], al[4];
#pragma unroll
        for (int i = 0; i < 4; i++) {
            size_t aidx = ((size_t)kb * mtcnt + mtBase + i) * 32 + lane;
            ah[i] = __ldg(&AfHi[aidx]);
            al[i] = __ldg(&AfLo[aidx]);
        }
#pragma unroll
        for (int j = 0; j < 8; j++) {
            uint4 bv = __ldg(&Bf[((size_t)kb * nbcnt + nbBase + j) * 32 + lane]);
#pragma unroll
            for (int i = 0; i < 4; i++) {
                mma16(acc[i][j], ah[i].x, ah[i].y, ah[i].z, ah[i].w, bv.x, bv.y);
                mma16(acc[i][j], ah[i].x, ah[i].y, ah[i].z, ah[i].w, bv.z, bv.w);
                mma16(acc[i][j], al[i].x, al[i].y, al[i].z, al[i].w, bv.x, bv.y);
            }
        }
    }

#pragma unroll
    for (int i = 0; i < 4; i++) {
        int r0 = bm + (wm * 4 + i) * 16 + gr;
#pragma unroll
        for (int j = 0; j < 8; j++) {
            int c = bn + wn * 64 + j * 8 + 2 * q;
            float bb0 = 0.f, bb1 = 0.f;
            if (bias1) { bb0 += bias1[c]; bb1 += bias1[c + 1]; }
            if (bias2) { bb0 += bias2[c]; bb1 += bias2[c + 1]; }
            float v00 = acc[i][j][0] + bb0, v01 = acc[i][j][1] + bb1;
            float v10 = acc[i][j][2] + bb0, v11 = acc[i][j][3] + bb1;
            if (relu) {
                v00 = fmaxf(v00, 0.f); v01 = fmaxf(v01, 0.f);
                v10 = fmaxf(v10, 0.f); v11 = fmaxf(v11, 0.f);
            }
            int r1 = r0 + 8;
            if (omode == 2) {
                size_t o00 = ((size_t)(r0 >> 6) * GATE4 + c) * 64 + (r0 & 63);
                size_t o10 = ((size_t)(r1 >> 6) * GATE4 + c) * 64 + (r1 & 63);
                C[o00]      = v00;
                C[o00 + 64] = v01;
                C[o10]      = v10;
                C[o10 + 64] = v11;
            } else if (omode == 1) {
                if (c < MELD) {
                    size_t or0 = (size_t)(r0 & 63) * TDEC + (r0 >> 6);
                    size_t or1 = (size_t)(r1 & 63) * TDEC + (r1 >> 6);
                    C[or0 * MELD + c]     = v00;
                    C[or0 * MELD + c + 1] = v01;
                    C[or1 * MELD + c]     = v10;
                    C[or1 * MELD + c + 1] = v11;
                }
            } else {
                C[(size_t)r0 * ldc + c]     = v00;
                C[(size_t)r0 * ldc + c + 1] = v01;
                C[(size_t)r1 * ldc + c]     = v10;
                C[(size_t)r1 * ldc + c + 1] = v11;
            }
        }
    }
}

// ---------- attention: logits via f16x2 tanh ----------
__global__ __launch_bounds__(256) void att_e_kernel(
    const float* __restrict__ Q, const float* __restrict__ PM,
    const float* __restrict__ v, float* __restrict__ E)
{
    __shared__ __half2 pm_s[64][65];
    __shared__ __half2 qs[4][64];
    __shared__ float v_s[128];
    int b = blockIdx.y, te0 = blockIdx.x * 64, tid = threadIdx.x;
    if (tid < 128) v_s[tid] = v[tid];
    for (int i = tid; i < 64 * 64; i += 256) {
        int r = i >> 6, c2 = i & 63;
        float2 f = *reinterpret_cast<const float2*>(
            PM + ((size_t)b * TENC + te0 + r) * ATTD + 2 * c2);
        pm_s[r][c2] = __floats2half2_rn(f.x, f.y);
    }
    int te = tid & 63, qq = tid >> 6;
    __syncthreads();
    for (int t0 = 0; t0 < TDEC; t0 += 4) {
        {
            int q = tid >> 6, c2 = tid & 63;
            float2 f = *reinterpret_cast<const float2*>(
                Q + ((size_t)(t0 + q) * 64 + b) * ATTD + 2 * c2);
            qs[q][c2] = __floats2half2_rn(f.x, f.y);
        }
        __syncthreads();
        float e = 0.f;
#pragma unroll 4
        for (int d2 = 0; d2 < 64; d2++) {
            __half2 x2 = __hadd2(qs[qq][d2], pm_s[te][d2]);
            uint32_t xi = *reinterpret_cast<uint32_t*>(&x2);
            uint32_t ti;
            asm("tanh.approx.f16x2 %0, %1;" : "=r"(ti) : "r"(xi));
            __half2 t2 = *reinterpret_cast<__half2*>(&ti);
            float2 tf = __half22float2(t2);
            e = fmaf(v_s[2 * d2], tf.x, e);
            e = fmaf(v_s[2 * d2 + 1], tf.y, e);
        }
        E[((size_t)(t0 + qq) * 64 + b) * TENC + te0 + te] = e;
        __syncthreads();
    }
}

__global__ __launch_bounds__(256) void att_softmax_kernel(
    const float* __restrict__ E, float* __restrict__ X, float* __restrict__ aligns)
{
    __shared__ float w_s[8][TENC];
    __shared__ float inv_s[8];
    int b = blockIdx.y, t0 = blockIdx.x * 8, tid = threadIdx.x;
    int warp = tid >> 5, lane = tid & 31;
    {
        int t = t0 + warp;
        size_t eb = ((size_t)t * 64 + b) * TENC;
        float m = -1e30f;
        for (int te = lane; te < TENC; te += 32) m = fmaxf(m, E[eb + te]);
#pragma unroll
        for (int o = 16; o; o >>= 1) m = fmaxf(m, __shfl_xor_sync(0xffffffffu, m, o));
        float s = 0.f;
        for (int te = lane; te < TENC; te += 32) {
            float w = __expf(E[eb + te] - m);
            w_s[warp][te] = w; s += w;
        }
#pragma unroll
        for (int o = 16; o; o >>= 1) s += __shfl_xor_sync(0xffffffffu, s, o);
        if (lane == 0) inv_s[warp] = 1.f / s;
    }
    __syncthreads();
    for (int i = tid; i < 8 * TENC; i += 256) {
        int q = i / TENC, te = i - q * TENC;
        float wv = w_s[q][te] * inv_s[q];
        int t = t0 + q;
        aligns[((size_t)b * TDEC + t) * TENC + te] = wv;
        X[((size_t)t * 64 + b) * KX + ATTD + te] = wv;
    }
}

// ---------- persistent LSTM: kb-split warps (R12 structure) ----------
__global__ __launch_bounds__(256, 1) void lstm_persistent_kernel(
    const float* __restrict__ G1, float* __restrict__ H)
{
    extern __shared__ uint4 smW[];
    __shared__ float st2[2][64][36];

    int tid = threadIdx.x;
    int warp = tid >> 5, lane = tid & 31;
    int gr = lane >> 2, q = lane & 3;
    int rt = warp & 3, kh = warp >> 2;
    int u0 = blockIdx.x * 8;
    int base = u0 >> 3;

    for (int i = tid; i < 64 * 4 * 32; i += 256) {
        int lane2 = i & 31, gate = (i >> 5) & 3, kb = i >> 7;
        smW[i] = __ldg(&g_WfHh[((size_t)kb * 512 + gate * 128 + base) * 32 + lane2]);
    }
    __syncthreads();

    int pb = tid & 63, pq = tid >> 6;
    float creg[2] = {0.f, 0.f};

    int p = (u0 >> 1) + pq;
    int kbW = p >> 3, qq = p & 7;
    int rtW = pb >> 4, rin = pb & 15;
    int comp = (qq < 4) ? ((rin < 8) ? 0 : 1) : ((rin < 8) ? 2 : 3);
    int laneW = (rin & 7) * 4 + (qq & 3);
    int fragIdx = ((kbW * 4 + rtW) * 32 + laneW) * 4 + comp;

    int kbeg = kh * 32;

    for (int t = 0; t < TDEC; t++) {
        float g1p[2][4];
        {
            size_t gb = (size_t)t * GATE4 * 64;
#pragma unroll
            for (int s = 0; s < 2; s++) {
                int u = u0 + 2 * pq + s;
                g1p[s][0] = __ldg(G1 + gb + (size_t)(0 * RNND + u) * 64 + pb);
                g1p[s][1] = __ldg(G1 + gb + (size_t)(1 * RNND + u) * 64 + pb);
                g1p[s][2] = __ldg(G1 + gb + (size_t)(2 * RNND + u) * 64 + pb);
                g1p[s][3] = __ldg(G1 + gb + (size_t)(3 * RNND + u) * 64 + pb);
            }
        }

        float acc[4][4];
#pragma unroll
        for (int g = 0; g < 4; g++)
#pragma unroll
            for (int r = 0; r < 4; r++) acc[g][r] = 0.f;

        if (t > 0) {
            int bufR = (t - 1) & 1;
            const uint4* AH = g_HfHi + (size_t)bufR * 64 * 4 * 32;
            const uint4* AL = g_HfLo + (size_t)bufR * 64 * 4 * 32;
#pragma unroll 8
            for (int kk = 0; kk < 32; kk++) {
                int kb = kbeg + kk;
                uint4 ah = __ldcg(AH + (kb * 4 + rt) * 32 + lane);
                uint4 al = __ldcg(AL + (kb * 4 + rt) * 32 + lane);
#pragma unroll
                for (int g = 0; g < 4; g++) {
                    uint4 b = smW[kb * 128 + g * 32 + lane];
                    mma16(acc[g], ah.x, ah.y, ah.z, ah.w, b.x, b.y);
                    mma16(acc[g], ah.x, ah.y, ah.z, ah.w, b.z, b.w);
                    mma16(acc[g], al.x, al.y, al.z, al.w, b.x, b.y);
                }
            }
        }

#pragma unroll
        for (int g = 0; g < 4; g++) {
            int c = g * 8 + 2 * q;
            int r0 = rt * 16 + gr;
            st2[kh][r0][c]         = acc[g][0];
            st2[kh][r0][c + 1]     = acc[g][1];
            st2[kh][r0 + 8][c]     = acc[g][2];
            st2[kh][r0 + 8][c + 1] = acc[g][3];
        }
        __syncthreads();

        float hpair[2];
#pragma unroll
        for (int s = 0; s < 2; s++) {
            int ul = 2 * pq + s;
            int u = u0 + ul;
            float gi = st2[0][pb][ul]      + st2[1][pb][ul]      + g1p[s][0];
            float gf = st2[0][pb][8 + ul]  + st2[1][pb][8 + ul]  + g1p[s][1];
            float gg = st2[0][pb][16 + ul] + st2[1][pb][16 + ul] + g1p[s][2];
            float go = st2[0][pb][24 + ul] + st2[1][pb][24 + ul] + g1p[s][3];
            float i_ = 1.f / (1.f + __expf(-gi));
            float f_ = 1.f / (1.f + __expf(-gf));
            float g_ = fast_tanh(gg);
            float o_ = 1.f / (1.f + __expf(-go));
            float cn = f_ * creg[s] + i_ * g_;
            creg[s] = cn;
            float hn = o_ * fast_tanh(cn);
            hpair[s] = hn;
            H[((size_t)t * 64 + pb) * RNND + u] = hn;
        }
        {
            int bufW = t & 1;
            uint32_t hi, lo;
            pack2(hpair[0], hpair[1], hi, lo);
            size_t off = (size_t)bufW * 64 * 4 * 32 * 4 + fragIdx;
            reinterpret_cast<uint32_t*>(g_HfHi)[off] = hi;
            reinterpret_cast<uint32_t*>(g_HfLo)[off] = lo;
        }
        __syncthreads();
        if (tid == 0) {
            asm volatile("red.release.gpu.global.add.u32 [%0], %1;"
                         :: "l"(&g_bar), "r"(1u) : "memory");
            unsigned tgt = (unsigned)NBLK * (unsigned)(t + 1);
            unsigned v;
            do {
                asm volatile("ld.global.acquire.gpu.u32 %0, [%1];" : "=r"(v) : "l"(&g_bar));
            } while (v < tgt);
        }
        __syncthreads();
    }
}

__global__ __launch_bounds__(256) void stop_kernel(
    const float* __restrict__ H, const float* __restrict__ sw,
    const float* __restrict__ sb, float* __restrict__ gout)
{
    int row = blockIdx.x * 8 + (threadIdx.x >> 5);
    int lane = threadIdx.x & 31;
    const float* h = H + (size_t)row * RNND;
    float acc = 0.f;
    for (int k = lane; k < RNND; k += 32) acc = fmaf(h[k], sw[k], acc);
#pragma unroll
    for (int o = 16; o; o >>= 1) acc += __shfl_xor_sync(0xffffffffu, acc, o);
    if (lane == 0) {
        int t = row >> 6, b = row & 63;
        gout[b * TDEC + t] = 1.f / (1.f + __expf(-(acc + sb[0])));
    }
}

extern "C" void kernel_launch(void* const* d_in, const int* in_sizes, int n_in,
                              void* d_out, int out_size) {
    const float* enc  = (const float*)d_in[0];
    const float* mel  = (const float*)d_in[1];
    const float* W1   = (const float*)d_in[4];
    const float* b1   = (const float*)d_in[5];
    const float* W2   = (const float*)d_in[6];
    const float* b2   = (const float*)d_in[7];
    const float* Wq   = (const float*)d_in[8];
    const float* Wm   = (const float*)d_in[9];
    const float* av   = (const float*)d_in[10];
    const float* Wih  = (const float*)d_in[11];
    const float* Whh  = (const float*)d_in[12];
    const float* bih  = (const float*)d_in[13];
    const float* bhh  = (const float*)d_in[14];
    const float* melW = (const float*)d_in[15];
    const float* melb = (const float*)d_in[16];
    const float* stW  = (const float*)d_in[17];
    const float* stb  = (const float*)d_in[18];
    float* out = (float*)d_out;

    float *P1, *P2, *Q, *PM, *E, *X, *G1, *H;
    uint4 *AfHi, *AfLo, *BfIh, *WfHh, *BfSm, *WaHi, *WaLo, *BfPM;
    cudaGetSymbolAddress((void**)&P1,  g_P1);
    cudaGetSymbolAddress((void**)&P2,  g_P2);
    cudaGetSymbolAddress((void**)&Q,   g_Q);
    cudaGetSymbolAddress((void**)&PM,  g_PM);
    cudaGetSymbolAddress((void**)&E,   g_E);
    cudaGetSymbolAddress((void**)&X,   g_X);
    cudaGetSymbolAddress((void**)&G1,  g_G1);
    cudaGetSymbolAddress((void**)&H,   g_H);
    cudaGetSymbolAddress((void**)&AfHi, g_AfHi);
    cudaGetSymbolAddress((void**)&AfLo, g_AfLo);
    cudaGetSymbolAddress((void**)&BfIh, g_BfIh);
    cudaGetSymbolAddress((void**)&WfHh, g_WfHh);
    cudaGetSymbolAddress((void**)&BfSm, g_BfSm);
    cudaGetSymbolAddress((void**)&WaHi, g_WaHi);
    cudaGetSymbolAddress((void**)&WaLo, g_WaLo);
    cudaGetSymbolAddress((void**)&BfPM, g_BfPM);

    static int attr_set = 0;
    if (!attr_set) {
        cudaFuncSetAttribute(lstm_persistent_kernel,
                             cudaFuncAttributeMaxDynamicSharedMemorySize, 131072);
        attr_set = 1;
    }

    zero_bar_kernel<<<1, 32>>>();

    // PM = enc @ Wm
    pack_afrag_kernel<<<(16*4608*32 + 255)/256, 256>>>(enc, 256, 16, 4608, AfHi, AfLo);
    pack_bfrag_kernel<<<(16*16*32 + 255)/256, 256>>>(Wm, BfSm, 16, 16, 128, 128);
    gemm_bf3_kernel<<<dim3(1, 288, 1), 256>>>(AfHi, AfLo, BfSm, PM, 128,
        16, 16, 4608, nullptr, nullptr, 0, 0, 0, 0, 0);

    // prenet chain: Pin -> P1 -> P2 -> Q
    prep_pin_frag_kernel<<<(5*1024*32 + 255)/256, 256>>>(mel);
    pack_bfrag_kernel<<<(5*32*32 + 255)/256, 256>>>(W1, BfSm, 5, 32, 256, 256);
    gemm_bf3_kernel<<<dim3(2, 64, 1), 256>>>(AfHi, AfLo, BfSm, P1, 256,
        5, 32, 1024, b1, nullptr, 1, 0, 0, 0, 0);
    pack_afrag_kernel<<<(16*1024*32 + 255)/256, 256>>>(P1, 256, 16, 1024, AfHi, AfLo);
    pack_bfrag_kernel<<<(16*32*32 + 255)/256, 256>>>(W2, BfSm, 16, 32, 256, 256);
    gemm_bf3_kernel<<<dim3(2, 64, 1), 256>>>(AfHi, AfLo, BfSm, P2, 256,
        16, 32, 1024, b2, nullptr, 1, 0, 0, 0, 0);
    pack_afrag_kernel<<<(16*1024*32 + 255)/256, 256>>>(P2, 256, 16, 1024, AfHi, AfLo);
    pack_bfrag_kernel<<<(16*16*32 + 255)/256, 256>>>(Wq, BfSm, 16, 16, 128, 128);
    gemm_bf3_kernel<<<dim3(1, 64, 1), 256>>>(AfHi, AfLo, BfSm, Q, 128,
        16, 16, 1024, nullptr, nullptr, 0, 0, 0, 0, 0);

    // attention
    att_e_kernel<<<dim3(TENC/64, BATCH), 256>>>(Q, PM, av, E);
    att_softmax_kernel<<<dim3(TDEC/8, BATCH), 256>>>(E, X, out + ALIGNS_OFF);

    // ctx = w @ PM per batch
    pack_w_kernel<<<dim3(144, 64), 256>>>(out + ALIGNS_OFF);
    pack_pm_kernel<<<dim3(144, 64), 256>>>(PM);
    gemm_bf3_kernel<<<dim3(1, 1, 64), 256>>>(WaHi, WaLo, BfPM, X, 64L * KX,
        72, 16, 16, nullptr, nullptr, 0, 0, 36864L, 36864L, (long)KX);

    // G1 = X @ Wih + b_ih + b_hh, transposed output (plain R12 gemm)
    pack_afrag_kernel<<<(80*1024*32 + 255)/256, 256>>>(X, KX, 80, 1024, AfHi, AfLo);
    pack_bfrag_kernel<<<(80*512*32 + 255)/256, 256>>>(Wih, BfIh, 80, 512, GATE4, GATE4);
    gemm_bf3_kernel<<<dim3(32, 64, 1), 256>>>(AfHi, AfLo, BfIh, G1, GATE4,
        80, 512, 1024, bih, bhh, 0, 2, 0, 0, 0);

    // recurrence
    pack_bfrag_kernel<<<(64*512*32 + 255)/256, 256>>>(Whh, WfHh, 64, 512, GATE4, GATE4);
    lstm_persistent_kernel<<<NBLK, 256, 131072>>>(G1, H);

    // mels = H @ melW + melb (tensor path, rowperm epilogue); melW frags reuse BfIh
    pack_afrag_kernel<<<(64*1024*32 + 255)/256, 256>>>(H, RNND, 64, 1024, AfHi, AfLo);
    pack_bfrag_kernel<<<(64*16*32 + 255)/256, 256>>>(melW, BfIh, 64, 16, MELD, MELD);
    gemm_bf3_kernel<<<dim3(1, 64, 1), 256>>>(AfHi, AfLo, BfIh, out, MELD,
        64, 16, 1024, melb, nullptr, 0, 1, 0, 0, 0);

    stop_kernel<<<ROWS/8, 256>>>(H, stW, stb, out + GATES_OFF);
}